// round 1
// baseline (speedup 1.0000x reference)
#include <cuda_runtime.h>
#include <math.h>

#define B_SZ  4
#define S_LEN 2048
#define DM    1024
#define NH    16
#define DK    64
#define MTOT  (B_SZ * S_LEN)   // 8192

// Scratch: head-split projections + pre-projection attention output.
__device__ float g_qh[(size_t)B_SZ * NH * S_LEN * DK];
__device__ float g_kh[(size_t)B_SZ * NH * S_LEN * DK];
__device__ float g_vh[(size_t)B_SZ * NH * S_LEN * DK];
__device__ float g_om[(size_t)MTOT * DM];

// C[m][n] = sum_k X[m][k] * W[n][k] + bias[n]   (torch Linear: x @ W.T + b)
// BM=128, BN=64, BK=16, 256 threads, 8x4 micro-tile per thread.
// HEAD_SPLIT=1: write to [B, H, S, DK] layout; else row-major [M, DM].
template<int HEAD_SPLIT>
__global__ void __launch_bounds__(256) gemm_k(const float* __restrict__ X,
                                              const float* __restrict__ W,
                                              const float* __restrict__ bias,
                                              float* __restrict__ out)
{
    __shared__ float Xs[16][132];   // [k][m], padded
    __shared__ float Ws[16][68];    // [k][n], padded

    const int tid = threadIdx.x;
    const int m0 = blockIdx.y * 128;
    const int n0 = blockIdx.x * 64;
    const int tr = tid >> 4;          // 0..15 -> rows tr*8..+7
    const int tc = tid & 15;          // 0..15 -> cols tc*4..+3
    const int lr = tid >> 2;          // 0..63 loader row
    const int lk = (tid & 3) << 2;    // 0,4,8,12 loader k-offset

    float acc[8][4];
#pragma unroll
    for (int i = 0; i < 8; ++i)
#pragma unroll
        for (int j = 0; j < 4; ++j) acc[i][j] = 0.f;

    const float* xp0 = X + (size_t)(m0 + lr) * DM + lk;
    const float* xp1 = X + (size_t)(m0 + lr + 64) * DM + lk;
    const float* wp  = W + (size_t)(n0 + lr) * DM + lk;

    for (int k0 = 0; k0 < DM; k0 += 16) {
        float4 x0 = *(const float4*)(xp0 + k0);
        float4 x1 = *(const float4*)(xp1 + k0);
        float4 wv = *(const float4*)(wp  + k0);
        Xs[lk + 0][lr] = x0.x; Xs[lk + 1][lr] = x0.y;
        Xs[lk + 2][lr] = x0.z; Xs[lk + 3][lr] = x0.w;
        Xs[lk + 0][lr + 64] = x1.x; Xs[lk + 1][lr + 64] = x1.y;
        Xs[lk + 2][lr + 64] = x1.z; Xs[lk + 3][lr + 64] = x1.w;
        Ws[lk + 0][lr] = wv.x; Ws[lk + 1][lr] = wv.y;
        Ws[lk + 2][lr] = wv.z; Ws[lk + 3][lr] = wv.w;
        __syncthreads();
#pragma unroll
        for (int kk = 0; kk < 16; ++kk) {
            float4 a0 = *(const float4*)&Xs[kk][tr * 8];
            float4 a1 = *(const float4*)&Xs[kk][tr * 8 + 4];
            float4 b4 = *(const float4*)&Ws[kk][tc * 4];
            float av[8] = {a0.x, a0.y, a0.z, a0.w, a1.x, a1.y, a1.z, a1.w};
            float bb[4] = {b4.x, b4.y, b4.z, b4.w};
#pragma unroll
            for (int i = 0; i < 8; ++i)
#pragma unroll
                for (int j = 0; j < 4; ++j)
                    acc[i][j] = fmaf(av[i], bb[j], acc[i][j]);
        }
        __syncthreads();
    }

    const int nbase = n0 + tc * 4;
    const float4 bl = *(const float4*)&bias[nbase];
#pragma unroll
    for (int i = 0; i < 8; ++i) {
        const int m = m0 + tr * 8 + i;
        float4 res;
        res.x = acc[i][0] + bl.x;
        res.y = acc[i][1] + bl.y;
        res.z = acc[i][2] + bl.z;
        res.w = acc[i][3] + bl.w;
        if (HEAD_SPLIT) {
            const int b = m >> 11;              // m / S_LEN
            const int s = m & (S_LEN - 1);
            const int h = nbase >> 6;           // n / DK
            const int d = nbase & 63;
            *(float4*)&out[(((size_t)(b * NH + h)) * S_LEN + s) * DK + d] = res;
        } else {
            *(float4*)&out[(size_t)m * DM + nbase] = res;
        }
    }
}

// Flash-attention style fused attention. grid = (S/64, B*H), 256 threads.
// Per block: 64 queries x full key loop in 64-key tiles; online softmax with
// register-replicated (m, l) per row; O accumulated in registers (4x4/thread).
__global__ void __launch_bounds__(256) attn_k(const float* __restrict__ Qh,
                                              const float* __restrict__ Kh,
                                              const float* __restrict__ Vh,
                                              const int* __restrict__ mask,
                                              float* __restrict__ om)
{
    extern __shared__ float sm[];
    float* Qs = sm;                  // [d][m] 64x68 (transposed)
    float* Ks = Qs + 64 * 68;        // [d][n] (transposed)
    float* Vs = Ks + 64 * 68;        // [n][d]
    float* Ps = Vs + 64 * 68;        // [n][m] (transposed probabilities)
    int*   msk = (int*)(Ps + 64 * 68);

    const int tid = threadIdx.x;
    const int bh = blockIdx.y;
    const int bb = bh >> 4;          // batch
    const int hh = bh & 15;          // head
    const int q0 = blockIdx.x * 64;
    const float* Q = Qh + (size_t)bh * S_LEN * DK;
    const float* K = Kh + (size_t)bh * S_LEN * DK;
    const float* V = Vh + (size_t)bh * S_LEN * DK;
    const int* mrow = mask + bb * S_LEN;

    const int tr = tid >> 4;         // rows tr*4..+3
    const int tc = tid & 15;         // cols tc*4..+3
    const int lr = tid >> 2;         // loader row 0..63
    const int ld = (tid & 3) << 4;   // loader d offset: 0,16,32,48

    // Load Q tile transposed: Qs[d][m]
    {
        const float* qp = Q + (size_t)(q0 + lr) * DK + ld;
#pragma unroll
        for (int u = 0; u < 4; ++u) {
            float4 v4 = *(const float4*)(qp + u * 4);
            const int d = ld + u * 4;
            Qs[(d + 0) * 68 + lr] = v4.x;
            Qs[(d + 1) * 68 + lr] = v4.y;
            Qs[(d + 2) * 68 + lr] = v4.z;
            Qs[(d + 3) * 68 + lr] = v4.w;
        }
    }

    float m_run[4], l_run[4], o[4][4];
#pragma unroll
    for (int i = 0; i < 4; ++i) {
        m_run[i] = -INFINITY;
        l_run[i] = 0.f;
#pragma unroll
        for (int j = 0; j < 4; ++j) o[i][j] = 0.f;
    }

    for (int kt = 0; kt < S_LEN; kt += 64) {
        // Load K (transposed) and V tiles + mask slice
        const float* kp = K + (size_t)(kt + lr) * DK + ld;
        const float* vp = V + (size_t)(kt + lr) * DK + ld;
#pragma unroll
        for (int u = 0; u < 4; ++u) {
            float4 kv = *(const float4*)(kp + u * 4);
            const int d = ld + u * 4;
            Ks[(d + 0) * 68 + lr] = kv.x;
            Ks[(d + 1) * 68 + lr] = kv.y;
            Ks[(d + 2) * 68 + lr] = kv.z;
            Ks[(d + 3) * 68 + lr] = kv.w;
            float4 vv = *(const float4*)(vp + u * 4);
            *(float4*)&Vs[lr * 68 + ld + u * 4] = vv;
        }
        if (tid < 64) msk[tid] = mrow[kt + tid];
        __syncthreads();

        // S = Q K^T (4x4 micro-tile per thread)
        float sv[4][4];
#pragma unroll
        for (int i = 0; i < 4; ++i)
#pragma unroll
            for (int j = 0; j < 4; ++j) sv[i][j] = 0.f;
#pragma unroll
        for (int kk = 0; kk < 64; ++kk) {
            float4 a = *(const float4*)&Qs[kk * 68 + tr * 4];
            float4 b = *(const float4*)&Ks[kk * 68 + tc * 4];
            float av[4] = {a.x, a.y, a.z, a.w};
            float bv[4] = {b.x, b.y, b.z, b.w};
#pragma unroll
            for (int i = 0; i < 4; ++i)
#pragma unroll
                for (int j = 0; j < 4; ++j)
                    sv[i][j] = fmaf(av[i], bv[j], sv[i][j]);
        }

        // scale (1/sqrt(64)) + mask
#pragma unroll
        for (int j = 0; j < 4; ++j) {
            const bool live = (msk[tc * 4 + j] != 0);
#pragma unroll
            for (int i = 0; i < 4; ++i)
                sv[i][j] = live ? sv[i][j] * 0.125f : -1e9f;
        }

        // Row max over 64 keys: local max4 then butterfly over 16 lanes
        float tmax[4];
#pragma unroll
        for (int i = 0; i < 4; ++i)
            tmax[i] = fmaxf(fmaxf(sv[i][0], sv[i][1]), fmaxf(sv[i][2], sv[i][3]));
#pragma unroll
        for (int off = 1; off < 16; off <<= 1)
#pragma unroll
            for (int i = 0; i < 4; ++i)
                tmax[i] = fmaxf(tmax[i], __shfl_xor_sync(0xffffffffu, tmax[i], off));

        // Online softmax update (register-replicated across the 16 row threads)
        float facv[4], psum[4];
#pragma unroll
        for (int i = 0; i < 4; ++i) {
            const float nm = fmaxf(m_run[i], tmax[i]);
            facv[i] = __expf(m_run[i] - nm);
            m_run[i] = nm;
            const float p0 = __expf(sv[i][0] - nm);
            const float p1 = __expf(sv[i][1] - nm);
            const float p2 = __expf(sv[i][2] - nm);
            const float p3 = __expf(sv[i][3] - nm);
            Ps[(tc * 4 + 0) * 68 + tr * 4 + i] = p0;
            Ps[(tc * 4 + 1) * 68 + tr * 4 + i] = p1;
            Ps[(tc * 4 + 2) * 68 + tr * 4 + i] = p2;
            Ps[(tc * 4 + 3) * 68 + tr * 4 + i] = p3;
            psum[i] = (p0 + p1) + (p2 + p3);
        }
#pragma unroll
        for (int off = 1; off < 16; off <<= 1)
#pragma unroll
            for (int i = 0; i < 4; ++i)
                psum[i] += __shfl_xor_sync(0xffffffffu, psum[i], off);
#pragma unroll
        for (int i = 0; i < 4; ++i)
            l_run[i] = l_run[i] * facv[i] + psum[i];

        __syncthreads();   // Ps visible to all

        // Rescale accumulator, then O += P @ V
#pragma unroll
        for (int i = 0; i < 4; ++i)
#pragma unroll
            for (int j = 0; j < 4; ++j) o[i][j] *= facv[i];
#pragma unroll 8
        for (int n = 0; n < 64; ++n) {
            float4 p4 = *(const float4*)&Ps[n * 68 + tr * 4];
            float4 v4 = *(const float4*)&Vs[n * 68 + tc * 4];
            float pv[4] = {p4.x, p4.y, p4.z, p4.w};
            float vv[4] = {v4.x, v4.y, v4.z, v4.w};
#pragma unroll
            for (int i = 0; i < 4; ++i)
#pragma unroll
                for (int j = 0; j < 4; ++j)
                    o[i][j] = fmaf(pv[i], vv[j], o[i][j]);
        }
        __syncthreads();   // done with Ks/Vs/Ps before next tile overwrites
    }

    // Normalize and store in [B, S, DM] layout (heads re-concatenated)
#pragma unroll
    for (int i = 0; i < 4; ++i) {
        const float inv = 1.f / l_run[i];
        const int s = q0 + tr * 4 + i;
        float4 res;
        res.x = o[i][0] * inv;
        res.y = o[i][1] * inv;
        res.z = o[i][2] * inv;
        res.w = o[i][3] * inv;
        *(float4*)&om[((size_t)(bb * S_LEN + s)) * DM + hh * 64 + tc * 4] = res;
    }
}

extern "C" void kernel_launch(void* const* d_in, const int* in_sizes, int n_in,
                              void* d_out, int out_size) {
    const float* q  = (const float*)d_in[0];
    const float* k  = (const float*)d_in[1];
    const float* v  = (const float*)d_in[2];
    const int*   mk = (const int*)  d_in[3];
    const float* wq = (const float*)d_in[4];
    const float* bq = (const float*)d_in[5];
    const float* wk = (const float*)d_in[6];
    const float* bk = (const float*)d_in[7];
    const float* wv = (const float*)d_in[8];
    const float* bv = (const float*)d_in[9];
    const float* wo = (const float*)d_in[10];
    const float* bo = (const float*)d_in[11];
    float* out = (float*)d_out;

    float *qh, *kh, *vh, *om;
    cudaGetSymbolAddress((void**)&qh, g_qh);
    cudaGetSymbolAddress((void**)&kh, g_kh);
    cudaGetSymbolAddress((void**)&vh, g_vh);
    cudaGetSymbolAddress((void**)&om, g_om);

    const size_t attn_smem = (size_t)(4 * 64 * 68) * sizeof(float) + 64 * sizeof(int);
    cudaFuncSetAttribute(attn_k, cudaFuncAttributeMaxDynamicSharedMemorySize, (int)attn_smem);

    dim3 gg(DM / 64, MTOT / 128);          // (16, 64)
    gemm_k<1><<<gg, 256>>>(q, wq, bq, qh);
    gemm_k<1><<<gg, 256>>>(k, wk, bk, kh);
    gemm_k<1><<<gg, 256>>>(v, wv, bv, vh);

    dim3 ga(S_LEN / 64, B_SZ * NH);        // (32, 64)
    attn_k<<<ga, 256, attn_smem>>>(qh, kh, vh, mk, om);

    gemm_k<0><<<gg, 256>>>(om, wo, bo, out);
}

// round 3
// speedup vs baseline: 1.2572x; 1.2572x over previous
#include <cuda_runtime.h>
#include <cuda_bf16.h>
#include <math.h>
#include <cstdint>

#define B_SZ  4
#define S_LEN 2048
#define DM    1024
#define NH    16
#define DK    64
#define MTOT  (B_SZ * S_LEN)   // 8192

// ---------------- scratch (device globals; no allocs allowed) ----------------
__device__ float g_qh[(size_t)B_SZ * NH * S_LEN * DK];
__device__ float g_kh[(size_t)B_SZ * NH * S_LEN * DK];
__device__ float g_vh[(size_t)B_SZ * NH * S_LEN * DK];
__device__ float g_om[(size_t)MTOT * DM];
__device__ __nv_bfloat16 g_xh[(size_t)MTOT * DM];
__device__ __nv_bfloat16 g_xl[(size_t)MTOT * DM];
__device__ __nv_bfloat16 g_wh[(size_t)DM * DM];
__device__ __nv_bfloat16 g_wl[(size_t)DM * DM];

// ---------------- helpers ----------------
__device__ __forceinline__ uint32_t smem_u32(const void* p) {
    uint32_t a;
    asm("{ .reg .u64 t; cvta.to.shared.u64 t, %1; cvt.u32.u64 %0, t; }" : "=r"(a) : "l"(p));
    return a;
}
__device__ __forceinline__ void cp16(uint32_t dst, const void* src) {
    asm volatile("cp.async.cg.shared.global [%0], [%1], 16;" :: "r"(dst), "l"(src) : "memory");
}
#define CP_COMMIT() asm volatile("cp.async.commit_group;" ::: "memory")
#define CP_WAIT(n)  asm volatile("cp.async.wait_group %0;" :: "n"(n) : "memory")

__device__ __forceinline__ void mma_bf16(float* d, const uint32_t* a, const uint32_t* b) {
    asm volatile(
        "mma.sync.aligned.m16n8k16.row.col.f32.bf16.bf16.f32 "
        "{%0,%1,%2,%3}, {%4,%5,%6,%7}, {%8,%9}, {%0,%1,%2,%3};"
        : "+f"(d[0]), "+f"(d[1]), "+f"(d[2]), "+f"(d[3])
        : "r"(a[0]), "r"(a[1]), "r"(a[2]), "r"(a[3]), "r"(b[0]), "r"(b[1]));
}

// ---------------- fp32 -> bf16 hi/lo split ----------------
__global__ void __launch_bounds__(256) split_k(const float* __restrict__ x,
                                               __nv_bfloat16* __restrict__ hi,
                                               __nv_bfloat16* __restrict__ lo,
                                               int n4)
{
    int i = blockIdx.x * 256 + threadIdx.x;
    if (i >= n4) return;
    float4 v = ((const float4*)x)[i];
    __nv_bfloat16 h0 = __float2bfloat16(v.x);
    __nv_bfloat16 h1 = __float2bfloat16(v.y);
    __nv_bfloat16 h2 = __float2bfloat16(v.z);
    __nv_bfloat16 h3 = __float2bfloat16(v.w);
    __nv_bfloat16 l0 = __float2bfloat16(v.x - __bfloat162float(h0));
    __nv_bfloat16 l1 = __float2bfloat16(v.y - __bfloat162float(h1));
    __nv_bfloat16 l2 = __float2bfloat16(v.z - __bfloat162float(h2));
    __nv_bfloat16 l3 = __float2bfloat16(v.w - __bfloat162float(h3));
    ((__nv_bfloat162*)hi)[i * 2 + 0] = __nv_bfloat162(h0, h1);
    ((__nv_bfloat162*)hi)[i * 2 + 1] = __nv_bfloat162(h2, h3);
    ((__nv_bfloat162*)lo)[i * 2 + 0] = __nv_bfloat162(l0, l1);
    ((__nv_bfloat162*)lo)[i * 2 + 1] = __nv_bfloat162(l2, l3);
}

// ---------------- bf16x3 mma.sync GEMM ----------------
// C[m][n] = sum_k X[m][k]*W[n][k] + bias[n]  (both operands K-major row-major)
// CTA tile 128x128, BK=32, 256 threads (8 warps, 2m x 4n, warp tile 64x32).
#define BK        32
#define NCHUNK    (DM / BK)        // 32
#define ASTRIDE_B 80               // bytes per smem row (40 bf16, conflict-free)
#define TILE_B    (128 * ASTRIDE_B)   // 10240 bytes per tile
#define GSMEM     (2 * 4 * TILE_B)    // double buffer x {Ah,Al,Bh,Bl} = 81920

template<int HEAD_SPLIT>
__global__ void __launch_bounds__(256, 1) gemm_mma(const __nv_bfloat16* __restrict__ Ah,
                                                   const __nv_bfloat16* __restrict__ Al,
                                                   const __nv_bfloat16* __restrict__ Bh,
                                                   const __nv_bfloat16* __restrict__ Bl,
                                                   const float* __restrict__ bias,
                                                   float* __restrict__ out)
{
    extern __shared__ char smem[];
    const uint32_t smb = smem_u32(smem);
    const int tid = threadIdx.x;
    const int w   = tid >> 5;
    const int l   = tid & 31;
    const int m0  = blockIdx.y * 128;
    const int n0  = blockIdx.x * 128;
    const int wm  = (w & 1) * 64;      // warp m offset
    const int wn  = (w >> 1) * 32;     // warp n offset

    // loader mapping: 2 uint4 per thread per tile per chunk.
    // idx in [0,512): row = idx>>2, c16 = idx&3 (16-byte column within 64B row)
    const int i0 = tid, i1 = tid + 256;
    const int r0 = i0 >> 2, c0 = i0 & 3;
    const int r1 = i1 >> 2, c1 = i1 & 3;

    auto buf_off = [](int buf, int t) -> uint32_t {
        return (uint32_t)(buf * 4 + t) * TILE_B;
    };

    // issue async loads of chunk ck into buffer buf
    auto load_chunk = [&](int ck, int buf) {
        const size_t ko = (size_t)ck * BK;
        const __nv_bfloat16* ga_h = Ah + (size_t)(m0 + r0) * DM + ko + c0 * 8;
        const __nv_bfloat16* ga_h2= Ah + (size_t)(m0 + r1) * DM + ko + c1 * 8;
        const __nv_bfloat16* gb_h = Bh + (size_t)(n0 + r0) * DM + ko + c0 * 8;
        const __nv_bfloat16* gb_h2= Bh + (size_t)(n0 + r1) * DM + ko + c1 * 8;
        const __nv_bfloat16* ga_l = Al + (size_t)(m0 + r0) * DM + ko + c0 * 8;
        const __nv_bfloat16* ga_l2= Al + (size_t)(m0 + r1) * DM + ko + c1 * 8;
        const __nv_bfloat16* gb_l = Bl + (size_t)(n0 + r0) * DM + ko + c0 * 8;
        const __nv_bfloat16* gb_l2= Bl + (size_t)(n0 + r1) * DM + ko + c1 * 8;
        const uint32_t s0 = (uint32_t)r0 * ASTRIDE_B + c0 * 16;
        const uint32_t s1 = (uint32_t)r1 * ASTRIDE_B + c1 * 16;
        cp16(smb + buf_off(buf, 0) + s0, ga_h);
        cp16(smb + buf_off(buf, 0) + s1, ga_h2);
        cp16(smb + buf_off(buf, 1) + s0, ga_l);
        cp16(smb + buf_off(buf, 1) + s1, ga_l2);
        cp16(smb + buf_off(buf, 2) + s0, gb_h);
        cp16(smb + buf_off(buf, 2) + s1, gb_h2);
        cp16(smb + buf_off(buf, 3) + s0, gb_l);
        cp16(smb + buf_off(buf, 3) + s1, gb_l2);
        CP_COMMIT();
    };

    float acc[4][4][4];
#pragma unroll
    for (int mi = 0; mi < 4; ++mi)
#pragma unroll
        for (int ni = 0; ni < 4; ++ni)
#pragma unroll
            for (int j = 0; j < 4; ++j) acc[mi][ni][j] = 0.f;

    load_chunk(0, 0);

    const int lr = l >> 2;          // fragment row within 8
    const int lc = (l & 3) * 4;     // byte offset of k-pair within row

    for (int ck = 0; ck < NCHUNK; ++ck) {
        const int buf = ck & 1;
        if (ck + 1 < NCHUNK) {
            load_chunk(ck + 1, buf ^ 1);
            CP_WAIT(1);
        } else {
            CP_WAIT(0);
        }
        __syncthreads();

        const char* sAh = smem + buf_off(buf, 0);
        const char* sAl = smem + buf_off(buf, 1);
        const char* sBh = smem + buf_off(buf, 2);
        const char* sBl = smem + buf_off(buf, 3);

#pragma unroll
        for (int kk = 0; kk < BK; kk += 16) {
            uint32_t afh[4][4], afl[4][4], bfh[4][2], bfl[4][2];
#pragma unroll
            for (int mi = 0; mi < 4; ++mi) {
                const uint32_t base = (uint32_t)(wm + mi * 16 + lr) * ASTRIDE_B + kk * 2 + lc;
                afh[mi][0] = *(const uint32_t*)(sAh + base);
                afh[mi][1] = *(const uint32_t*)(sAh + base + 8 * ASTRIDE_B);
                afh[mi][2] = *(const uint32_t*)(sAh + base + 16);
                afh[mi][3] = *(const uint32_t*)(sAh + base + 8 * ASTRIDE_B + 16);
                afl[mi][0] = *(const uint32_t*)(sAl + base);
                afl[mi][1] = *(const uint32_t*)(sAl + base + 8 * ASTRIDE_B);
                afl[mi][2] = *(const uint32_t*)(sAl + base + 16);
                afl[mi][3] = *(const uint32_t*)(sAl + base + 8 * ASTRIDE_B + 16);
            }
#pragma unroll
            for (int ni = 0; ni < 4; ++ni) {
                const uint32_t base = (uint32_t)(wn + ni * 8 + lr) * ASTRIDE_B + kk * 2 + lc;
                bfh[ni][0] = *(const uint32_t*)(sBh + base);
                bfh[ni][1] = *(const uint32_t*)(sBh + base + 16);
                bfl[ni][0] = *(const uint32_t*)(sBl + base);
                bfl[ni][1] = *(const uint32_t*)(sBl + base + 16);
            }
#pragma unroll
            for (int mi = 0; mi < 4; ++mi)
#pragma unroll
                for (int ni = 0; ni < 4; ++ni) {
                    mma_bf16(acc[mi][ni], afh[mi], bfh[ni]);   // hi*hi
                    mma_bf16(acc[mi][ni], afh[mi], bfl[ni]);   // hi*lo
                    mma_bf16(acc[mi][ni], afl[mi], bfh[ni]);   // lo*hi
                }
        }
        __syncthreads();
    }

    // epilogue: c0,c1 -> (r, c..c+1); c2,c3 -> (r+8, c..c+1)
#pragma unroll
    for (int mi = 0; mi < 4; ++mi) {
        const int mrow = m0 + wm + mi * 16 + lr;
#pragma unroll
        for (int ni = 0; ni < 4; ++ni) {
            const int col = n0 + wn + ni * 8 + (l & 3) * 2;
            const float2 b2 = *(const float2*)&bias[col];
            float2 v0 = { acc[mi][ni][0] + b2.x, acc[mi][ni][1] + b2.y };
            float2 v1 = { acc[mi][ni][2] + b2.x, acc[mi][ni][3] + b2.y };
            if (HEAD_SPLIT) {
                const int b = mrow >> 11;
                const int s = mrow & (S_LEN - 1);
                const int hh = col >> 6, d = col & 63;
                *(float2*)&out[(((size_t)(b * NH + hh)) * S_LEN + s) * DK + d] = v0;
                *(float2*)&out[(((size_t)(b * NH + hh)) * S_LEN + s + 8) * DK + d] = v1;
            } else {
                *(float2*)&out[(size_t)mrow * DM + col] = v0;
                *(float2*)&out[(size_t)(mrow + 8) * DM + col] = v1;
            }
        }
    }
}

// ---------------- SIMT flash attention (unchanged) ----------------
__global__ void __launch_bounds__(256) attn_k(const float* __restrict__ Qh,
                                              const float* __restrict__ Kh,
                                              const float* __restrict__ Vh,
                                              const int* __restrict__ mask,
                                              float* __restrict__ om)
{
    extern __shared__ float sm[];
    float* Qs = sm;
    float* Ks = Qs + 64 * 68;
    float* Vs = Ks + 64 * 68;
    float* Ps = Vs + 64 * 68;
    int*   msk = (int*)(Ps + 64 * 68);

    const int tid = threadIdx.x;
    const int bh = blockIdx.y;
    const int bb = bh >> 4;
    const int hh = bh & 15;
    const int q0 = blockIdx.x * 64;
    const float* Q = Qh + (size_t)bh * S_LEN * DK;
    const float* K = Kh + (size_t)bh * S_LEN * DK;
    const float* V = Vh + (size_t)bh * S_LEN * DK;
    const int* mrow = mask + bb * S_LEN;

    const int tr = tid >> 4;
    const int tc = tid & 15;
    const int lr = tid >> 2;
    const int ld = (tid & 3) << 4;

    {
        const float* qp = Q + (size_t)(q0 + lr) * DK + ld;
#pragma unroll
        for (int u = 0; u < 4; ++u) {
            float4 v4 = *(const float4*)(qp + u * 4);
            const int d = ld + u * 4;
            Qs[(d + 0) * 68 + lr] = v4.x;
            Qs[(d + 1) * 68 + lr] = v4.y;
            Qs[(d + 2) * 68 + lr] = v4.z;
            Qs[(d + 3) * 68 + lr] = v4.w;
        }
    }

    float m_run[4], l_run[4], o[4][4];
#pragma unroll
    for (int i = 0; i < 4; ++i) {
        m_run[i] = -INFINITY;
        l_run[i] = 0.f;
#pragma unroll
        for (int j = 0; j < 4; ++j) o[i][j] = 0.f;
    }

    for (int kt = 0; kt < S_LEN; kt += 64) {
        const float* kp = K + (size_t)(kt + lr) * DK + ld;
        const float* vp = V + (size_t)(kt + lr) * DK + ld;
#pragma unroll
        for (int u = 0; u < 4; ++u) {
            float4 kv = *(const float4*)(kp + u * 4);
            const int d = ld + u * 4;
            Ks[(d + 0) * 68 + lr] = kv.x;
            Ks[(d + 1) * 68 + lr] = kv.y;
            Ks[(d + 2) * 68 + lr] = kv.z;
            Ks[(d + 3) * 68 + lr] = kv.w;
            float4 vv = *(const float4*)(vp + u * 4);
            *(float4*)&Vs[lr * 68 + ld + u * 4] = vv;
        }
        if (tid < 64) msk[tid] = mrow[kt + tid];
        __syncthreads();

        float sv[4][4];
#pragma unroll
        for (int i = 0; i < 4; ++i)
#pragma unroll
            for (int j = 0; j < 4; ++j) sv[i][j] = 0.f;
#pragma unroll
        for (int kk = 0; kk < 64; ++kk) {
            float4 a = *(const float4*)&Qs[kk * 68 + tr * 4];
            float4 b = *(const float4*)&Ks[kk * 68 + tc * 4];
            float av[4] = {a.x, a.y, a.z, a.w};
            float bv[4] = {b.x, b.y, b.z, b.w};
#pragma unroll
            for (int i = 0; i < 4; ++i)
#pragma unroll
                for (int j = 0; j < 4; ++j)
                    sv[i][j] = fmaf(av[i], bv[j], sv[i][j]);
        }

#pragma unroll
        for (int j = 0; j < 4; ++j) {
            const bool live = (msk[tc * 4 + j] != 0);
#pragma unroll
            for (int i = 0; i < 4; ++i)
                sv[i][j] = live ? sv[i][j] * 0.125f : -1e9f;
        }

        float tmax[4];
#pragma unroll
        for (int i = 0; i < 4; ++i)
            tmax[i] = fmaxf(fmaxf(sv[i][0], sv[i][1]), fmaxf(sv[i][2], sv[i][3]));
#pragma unroll
        for (int off = 1; off < 16; off <<= 1)
#pragma unroll
            for (int i = 0; i < 4; ++i)
                tmax[i] = fmaxf(tmax[i], __shfl_xor_sync(0xffffffffu, tmax[i], off));

        float facv[4], psum[4];
#pragma unroll
        for (int i = 0; i < 4; ++i) {
            const float nm = fmaxf(m_run[i], tmax[i]);
            facv[i] = __expf(m_run[i] - nm);
            m_run[i] = nm;
            const float p0 = __expf(sv[i][0] - nm);
            const float p1 = __expf(sv[i][1] - nm);
            const float p2 = __expf(sv[i][2] - nm);
            const float p3 = __expf(sv[i][3] - nm);
            Ps[(tc * 4 + 0) * 68 + tr * 4 + i] = p0;
            Ps[(tc * 4 + 1) * 68 + tr * 4 + i] = p1;
            Ps[(tc * 4 + 2) * 68 + tr * 4 + i] = p2;
            Ps[(tc * 4 + 3) * 68 + tr * 4 + i] = p3;
            psum[i] = (p0 + p1) + (p2 + p3);
        }
#pragma unroll
        for (int off = 1; off < 16; off <<= 1)
#pragma unroll
            for (int i = 0; i < 4; ++i)
                psum[i] += __shfl_xor_sync(0xffffffffu, psum[i], off);
#pragma unroll
        for (int i = 0; i < 4; ++i)
            l_run[i] = l_run[i] * facv[i] + psum[i];

        __syncthreads();

#pragma unroll
        for (int i = 0; i < 4; ++i)
#pragma unroll
            for (int j = 0; j < 4; ++j) o[i][j] *= facv[i];
#pragma unroll 8
        for (int n = 0; n < 64; ++n) {
            float4 p4 = *(const float4*)&Ps[n * 68 + tr * 4];
            float4 v4 = *(const float4*)&Vs[n * 68 + tc * 4];
            float pv[4] = {p4.x, p4.y, p4.z, p4.w};
            float vv[4] = {v4.x, v4.y, v4.z, v4.w};
#pragma unroll
            for (int i = 0; i < 4; ++i)
#pragma unroll
                for (int j = 0; j < 4; ++j)
                    o[i][j] = fmaf(pv[i], vv[j], o[i][j]);
        }
        __syncthreads();
    }

#pragma unroll
    for (int i = 0; i < 4; ++i) {
        const float inv = 1.f / l_run[i];
        const int s = q0 + tr * 4 + i;
        float4 res;
        res.x = o[i][0] * inv;
        res.y = o[i][1] * inv;
        res.z = o[i][2] * inv;
        res.w = o[i][3] * inv;
        *(float4*)&om[((size_t)(bb * S_LEN + s)) * DM + hh * 64 + tc * 4] = res;
    }
}

// ---------------- launch ----------------
extern "C" void kernel_launch(void* const* d_in, const int* in_sizes, int n_in,
                              void* d_out, int out_size) {
    const float* q  = (const float*)d_in[0];
    const float* k  = (const float*)d_in[1];
    const float* v  = (const float*)d_in[2];
    const int*   mk = (const int*)  d_in[3];
    const float* wq = (const float*)d_in[4];
    const float* bq = (const float*)d_in[5];
    const float* wk = (const float*)d_in[6];
    const float* bk = (const float*)d_in[7];
    const float* wv = (const float*)d_in[8];
    const float* bv = (const float*)d_in[9];
    const float* wo = (const float*)d_in[10];
    const float* bo = (const float*)d_in[11];
    float* out = (float*)d_out;

    float *qh, *kh, *vh, *om;
    __nv_bfloat16 *xh, *xl, *wh, *wl;
    cudaGetSymbolAddress((void**)&qh, g_qh);
    cudaGetSymbolAddress((void**)&kh, g_kh);
    cudaGetSymbolAddress((void**)&vh, g_vh);
    cudaGetSymbolAddress((void**)&om, g_om);
    cudaGetSymbolAddress((void**)&xh, g_xh);
    cudaGetSymbolAddress((void**)&xl, g_xl);
    cudaGetSymbolAddress((void**)&wh, g_wh);
    cudaGetSymbolAddress((void**)&wl, g_wl);

    cudaFuncSetAttribute(gemm_mma<0>, cudaFuncAttributeMaxDynamicSharedMemorySize, GSMEM);
    cudaFuncSetAttribute(gemm_mma<1>, cudaFuncAttributeMaxDynamicSharedMemorySize, GSMEM);
    const size_t attn_smem = (size_t)(4 * 64 * 68) * sizeof(float) + 64 * sizeof(int);
    cudaFuncSetAttribute(attn_k, cudaFuncAttributeMaxDynamicSharedMemorySize, (int)attn_smem);

    const int nx4 = MTOT * DM / 4;
    const int nw4 = DM * DM / 4;
    dim3 gg(DM / 128, MTOT / 128);     // (8, 64)

    // Q projection
    split_k<<<(nx4 + 255) / 256, 256>>>(q, xh, xl, nx4);
    split_k<<<(nw4 + 255) / 256, 256>>>(wq, wh, wl, nw4);
    gemm_mma<1><<<gg, 256, GSMEM>>>(xh, xl, wh, wl, bq, qh);
    // K projection
    split_k<<<(nx4 + 255) / 256, 256>>>(k, xh, xl, nx4);
    split_k<<<(nw4 + 255) / 256, 256>>>(wk, wh, wl, nw4);
    gemm_mma<1><<<gg, 256, GSMEM>>>(xh, xl, wh, wl, bk, kh);
    // V projection
    split_k<<<(nx4 + 255) / 256, 256>>>(v, xh, xl, nx4);
    split_k<<<(nw4 + 255) / 256, 256>>>(wv, wh, wl, nw4);
    gemm_mma<1><<<gg, 256, GSMEM>>>(xh, xl, wh, wl, bv, vh);

    // attention
    dim3 ga(S_LEN / 64, B_SZ * NH);
    attn_k<<<ga, 256, attn_smem>>>(qh, kh, vh, mk, om);

    // output projection
    split_k<<<(nx4 + 255) / 256, 256>>>(om, xh, xl, nx4);
    split_k<<<(nw4 + 255) / 256, 256>>>(wo, wh, wl, nw4);
    gemm_mma<0><<<gg, 256, GSMEM>>>(xh, xl, wh, wl, bo, out);
}

// round 4
// speedup vs baseline: 2.5829x; 2.0544x over previous
#include <cuda_runtime.h>
#include <cuda_bf16.h>
#include <math.h>
#include <cstdint>

#define B_SZ  4
#define S_LEN 2048
#define DM    1024
#define NH    16
#define DK    64
#define MTOT  (B_SZ * S_LEN)   // 8192

// ---------------- scratch (device globals) ----------------
__device__ __nv_bfloat16 g_xh[(size_t)MTOT * DM];
__device__ __nv_bfloat16 g_xl[(size_t)MTOT * DM];
__device__ __nv_bfloat16 g_wh[(size_t)DM * DM];
__device__ __nv_bfloat16 g_wl[(size_t)DM * DM];
__device__ __nv_bfloat16 g_qhh[(size_t)B_SZ * NH * S_LEN * DK];
__device__ __nv_bfloat16 g_qhl[(size_t)B_SZ * NH * S_LEN * DK];
__device__ __nv_bfloat16 g_khh[(size_t)B_SZ * NH * S_LEN * DK];
__device__ __nv_bfloat16 g_khl[(size_t)B_SZ * NH * S_LEN * DK];
__device__ __nv_bfloat16 g_vth[(size_t)B_SZ * NH * DK * S_LEN];
__device__ __nv_bfloat16 g_vtl[(size_t)B_SZ * NH * DK * S_LEN];
__device__ __nv_bfloat16 g_omh[(size_t)MTOT * DM];
__device__ __nv_bfloat16 g_oml[(size_t)MTOT * DM];

// ---------------- helpers ----------------
__device__ __forceinline__ uint32_t smem_u32(const void* p) {
    uint32_t a;
    asm("{ .reg .u64 t; cvta.to.shared.u64 t, %1; cvt.u32.u64 %0, t; }" : "=r"(a) : "l"(p));
    return a;
}
__device__ __forceinline__ void cp16(uint32_t dst, const void* src) {
    asm volatile("cp.async.cg.shared.global [%0], [%1], 16;" :: "r"(dst), "l"(src) : "memory");
}
#define CP_COMMIT() asm volatile("cp.async.commit_group;" ::: "memory")
#define CP_WAIT(n)  asm volatile("cp.async.wait_group %0;" :: "n"(n) : "memory")

__device__ __forceinline__ void mma_bf16(float* d, const uint32_t* a, const uint32_t* b) {
    asm volatile(
        "mma.sync.aligned.m16n8k16.row.col.f32.bf16.bf16.f32 "
        "{%0,%1,%2,%3}, {%4,%5,%6,%7}, {%8,%9}, {%0,%1,%2,%3};"
        : "+f"(d[0]), "+f"(d[1]), "+f"(d[2]), "+f"(d[3])
        : "r"(a[0]), "r"(a[1]), "r"(a[2]), "r"(a[3]), "r"(b[0]), "r"(b[1]));
}
__device__ __forceinline__ uint32_t packbf(float a, float b) {
    __nv_bfloat162 t = __floats2bfloat162_rn(a, b);
    return *(uint32_t*)&t;
}

// ---------------- fp32 -> bf16 hi/lo split ----------------
__global__ void __launch_bounds__(256) split_k(const float* __restrict__ x,
                                               __nv_bfloat16* __restrict__ hi,
                                               __nv_bfloat16* __restrict__ lo,
                                               int n4)
{
    int i = blockIdx.x * 256 + threadIdx.x;
    if (i >= n4) return;
    float4 v = ((const float4*)x)[i];
    __nv_bfloat16 h0 = __float2bfloat16(v.x);
    __nv_bfloat16 h1 = __float2bfloat16(v.y);
    __nv_bfloat16 h2 = __float2bfloat16(v.z);
    __nv_bfloat16 h3 = __float2bfloat16(v.w);
    __nv_bfloat16 l0 = __float2bfloat16(v.x - __bfloat162float(h0));
    __nv_bfloat16 l1 = __float2bfloat16(v.y - __bfloat162float(h1));
    __nv_bfloat16 l2 = __float2bfloat16(v.z - __bfloat162float(h2));
    __nv_bfloat16 l3 = __float2bfloat16(v.w - __bfloat162float(h3));
    ((__nv_bfloat162*)hi)[i * 2 + 0] = __nv_bfloat162(h0, h1);
    ((__nv_bfloat162*)hi)[i * 2 + 1] = __nv_bfloat162(h2, h3);
    ((__nv_bfloat162*)lo)[i * 2 + 0] = __nv_bfloat162(l0, l1);
    ((__nv_bfloat162*)lo)[i * 2 + 1] = __nv_bfloat162(l2, l3);
}

// ---------------- bf16x3 mma.sync GEMM ----------------
// EPI: 0 = fp32 row-major out; 1 = head-split bf16 hi/lo [bh][s][d];
//      2 = transposed bf16 hi/lo [bh][d][s]
#define BK        32
#define NCHUNK    (DM / BK)
#define ASTRIDE_B 80
#define TILE_B    (128 * ASTRIDE_B)
#define GSMEM     (2 * 4 * TILE_B)

template<int EPI>
__global__ void __launch_bounds__(256, 1) gemm_mma(const __nv_bfloat16* __restrict__ Ah,
                                                   const __nv_bfloat16* __restrict__ Al,
                                                   const __nv_bfloat16* __restrict__ Bh,
                                                   const __nv_bfloat16* __restrict__ Bl,
                                                   const float* __restrict__ bias,
                                                   float* __restrict__ out,
                                                   __nv_bfloat16* __restrict__ oh,
                                                   __nv_bfloat16* __restrict__ ol)
{
    extern __shared__ char smem[];
    const uint32_t smb = smem_u32(smem);
    const int tid = threadIdx.x;
    const int w   = tid >> 5;
    const int l   = tid & 31;
    const int m0  = blockIdx.y * 128;
    const int n0  = blockIdx.x * 128;
    const int wm  = (w & 1) * 64;
    const int wn  = (w >> 1) * 32;

    const int i0 = tid, i1 = tid + 256;
    const int r0 = i0 >> 2, c0 = i0 & 3;
    const int r1 = i1 >> 2, c1 = i1 & 3;

    auto buf_off = [](int buf, int t) -> uint32_t {
        return (uint32_t)(buf * 4 + t) * TILE_B;
    };

    auto load_chunk = [&](int ck, int buf) {
        const size_t ko = (size_t)ck * BK;
        const uint32_t s0 = (uint32_t)r0 * ASTRIDE_B + c0 * 16;
        const uint32_t s1 = (uint32_t)r1 * ASTRIDE_B + c1 * 16;
        cp16(smb + buf_off(buf, 0) + s0, Ah + (size_t)(m0 + r0) * DM + ko + c0 * 8);
        cp16(smb + buf_off(buf, 0) + s1, Ah + (size_t)(m0 + r1) * DM + ko + c1 * 8);
        cp16(smb + buf_off(buf, 1) + s0, Al + (size_t)(m0 + r0) * DM + ko + c0 * 8);
        cp16(smb + buf_off(buf, 1) + s1, Al + (size_t)(m0 + r1) * DM + ko + c1 * 8);
        cp16(smb + buf_off(buf, 2) + s0, Bh + (size_t)(n0 + r0) * DM + ko + c0 * 8);
        cp16(smb + buf_off(buf, 2) + s1, Bh + (size_t)(n0 + r1) * DM + ko + c1 * 8);
        cp16(smb + buf_off(buf, 3) + s0, Bl + (size_t)(n0 + r0) * DM + ko + c0 * 8);
        cp16(smb + buf_off(buf, 3) + s1, Bl + (size_t)(n0 + r1) * DM + ko + c1 * 8);
        CP_COMMIT();
    };

    float acc[4][4][4];
#pragma unroll
    for (int mi = 0; mi < 4; ++mi)
#pragma unroll
        for (int ni = 0; ni < 4; ++ni)
#pragma unroll
            for (int j = 0; j < 4; ++j) acc[mi][ni][j] = 0.f;

    load_chunk(0, 0);

    const int lr = l >> 2;
    const int lc = (l & 3) * 4;

    for (int ck = 0; ck < NCHUNK; ++ck) {
        const int buf = ck & 1;
        if (ck + 1 < NCHUNK) {
            load_chunk(ck + 1, buf ^ 1);
            CP_WAIT(1);
        } else {
            CP_WAIT(0);
        }
        __syncthreads();

        const char* sAh = smem + buf_off(buf, 0);
        const char* sAl = smem + buf_off(buf, 1);
        const char* sBh = smem + buf_off(buf, 2);
        const char* sBl = smem + buf_off(buf, 3);

#pragma unroll
        for (int kk = 0; kk < BK; kk += 16) {
            uint32_t afh[4][4], afl[4][4], bfh[4][2], bfl[4][2];
#pragma unroll
            for (int mi = 0; mi < 4; ++mi) {
                const uint32_t base = (uint32_t)(wm + mi * 16 + lr) * ASTRIDE_B + kk * 2 + lc;
                afh[mi][0] = *(const uint32_t*)(sAh + base);
                afh[mi][1] = *(const uint32_t*)(sAh + base + 8 * ASTRIDE_B);
                afh[mi][2] = *(const uint32_t*)(sAh + base + 16);
                afh[mi][3] = *(const uint32_t*)(sAh + base + 8 * ASTRIDE_B + 16);
                afl[mi][0] = *(const uint32_t*)(sAl + base);
                afl[mi][1] = *(const uint32_t*)(sAl + base + 8 * ASTRIDE_B);
                afl[mi][2] = *(const uint32_t*)(sAl + base + 16);
                afl[mi][3] = *(const uint32_t*)(sAl + base + 8 * ASTRIDE_B + 16);
            }
#pragma unroll
            for (int ni = 0; ni < 4; ++ni) {
                const uint32_t base = (uint32_t)(wn + ni * 8 + lr) * ASTRIDE_B + kk * 2 + lc;
                bfh[ni][0] = *(const uint32_t*)(sBh + base);
                bfh[ni][1] = *(const uint32_t*)(sBh + base + 16);
                bfl[ni][0] = *(const uint32_t*)(sBl + base);
                bfl[ni][1] = *(const uint32_t*)(sBl + base + 16);
            }
#pragma unroll
            for (int mi = 0; mi < 4; ++mi)
#pragma unroll
                for (int ni = 0; ni < 4; ++ni) {
                    mma_bf16(acc[mi][ni], afh[mi], bfh[ni]);
                    mma_bf16(acc[mi][ni], afh[mi], bfl[ni]);
                    mma_bf16(acc[mi][ni], afl[mi], bfh[ni]);
                }
        }
        __syncthreads();
    }

#pragma unroll
    for (int mi = 0; mi < 4; ++mi) {
        const int mrow = m0 + wm + mi * 16 + lr;
        const int b = mrow >> 11;
        const int s = mrow & (S_LEN - 1);
#pragma unroll
        for (int ni = 0; ni < 4; ++ni) {
            const int col = n0 + wn + ni * 8 + (l & 3) * 2;
            const float2 b2 = *(const float2*)&bias[col];
            float2 v0 = { acc[mi][ni][0] + b2.x, acc[mi][ni][1] + b2.y };
            float2 v1 = { acc[mi][ni][2] + b2.x, acc[mi][ni][3] + b2.y };
            if (EPI == 0) {
                *(float2*)&out[(size_t)mrow * DM + col] = v0;
                *(float2*)&out[(size_t)(mrow + 8) * DM + col] = v1;
            } else if (EPI == 1) {
                const int hh = col >> 6, d = col & 63;
                const size_t base = ((size_t)(b * NH + hh) * S_LEN + s) * DK + d;
                float hx = __bfloat162float(__float2bfloat16(v0.x));
                float hy = __bfloat162float(__float2bfloat16(v0.y));
                *(uint32_t*)&oh[base] = packbf(v0.x, v0.y);
                *(uint32_t*)&ol[base] = packbf(v0.x - hx, v0.y - hy);
                hx = __bfloat162float(__float2bfloat16(v1.x));
                hy = __bfloat162float(__float2bfloat16(v1.y));
                *(uint32_t*)&oh[base + 8 * DK] = packbf(v1.x, v1.y);
                *(uint32_t*)&ol[base + 8 * DK] = packbf(v1.x - hx, v1.y - hy);
            } else {
                const int hh = col >> 6, d = col & 63;
                const size_t rb = ((size_t)(b * NH + hh) * DK + d) * S_LEN;
                float h;
                h = __bfloat162float(__float2bfloat16(v0.x));
                oh[rb + s] = __float2bfloat16(v0.x);
                ol[rb + s] = __float2bfloat16(v0.x - h);
                h = __bfloat162float(__float2bfloat16(v0.y));
                oh[rb + S_LEN + s] = __float2bfloat16(v0.y);
                ol[rb + S_LEN + s] = __float2bfloat16(v0.y - h);
                h = __bfloat162float(__float2bfloat16(v1.x));
                oh[rb + s + 8] = __float2bfloat16(v1.x);
                ol[rb + s + 8] = __float2bfloat16(v1.x - h);
                h = __bfloat162float(__float2bfloat16(v1.y));
                oh[rb + S_LEN + s + 8] = __float2bfloat16(v1.y);
                ol[rb + S_LEN + s + 8] = __float2bfloat16(v1.y - h);
            }
        }
    }
}

// ---------------- mma.sync flash attention ----------------
// grid (S/128, B*H), 256 threads (8 warps x 16 q rows). 64-key tiles.
#define RSTR      144                      // padded smem row stride (bytes)
#define AOFF_QH   0                        // 128*144 = 18432
#define AOFF_QL   18432
#define AOFF_KH   36864                    // + buf*9216
#define AOFF_KL   55296
#define AOFF_VH   73728
#define AOFF_VL   92160
#define AOFF_MSK  110592
#define ASMEM     118784

__global__ void __launch_bounds__(256, 1) attn_mma(const __nv_bfloat16* __restrict__ Qhh,
                                                   const __nv_bfloat16* __restrict__ Qhl,
                                                   const __nv_bfloat16* __restrict__ Khh,
                                                   const __nv_bfloat16* __restrict__ Khl,
                                                   const __nv_bfloat16* __restrict__ Vth,
                                                   const __nv_bfloat16* __restrict__ Vtl,
                                                   const int* __restrict__ mask,
                                                   __nv_bfloat16* __restrict__ omh,
                                                   __nv_bfloat16* __restrict__ oml)
{
    extern __shared__ char smem[];
    const uint32_t smb = smem_u32(smem);
    const int tid = threadIdx.x;
    const int w   = tid >> 5;
    const int l   = tid & 31;
    const int bh  = blockIdx.y;
    const int bb  = bh >> 4;
    const int hh  = bh & 15;
    const int q0  = blockIdx.x * 128;
    const int wq0 = w * 16;
    const int r   = l >> 2;
    const int cg  = l & 3;

    // Q tile loads (group 1, together with KV tile 0)
#pragma unroll
    for (int p = 0; p < 4; ++p) {
        const int idx = tid + p * 256;        // 0..1023
        const int row = idx >> 3, ci = idx & 7;
        cp16(smb + AOFF_QH + row * RSTR + ci * 16,
             Qhh + ((size_t)bh * S_LEN + q0 + row) * DK + ci * 8);
        cp16(smb + AOFF_QL + row * RSTR + ci * 16,
             Qhl + ((size_t)bh * S_LEN + q0 + row) * DK + ci * 8);
    }

    auto load_kv = [&](int kt, int buf) {
#pragma unroll
        for (int p = 0; p < 2; ++p) {
            const int idx = tid + p * 256;    // 0..511
            const int row = idx >> 3, ci = idx & 7;
            const uint32_t dst = (uint32_t)row * RSTR + ci * 16 + buf * 9216;
            cp16(smb + AOFF_KH + dst, Khh + ((size_t)bh * S_LEN + kt + row) * DK + ci * 8);
            cp16(smb + AOFF_KL + dst, Khl + ((size_t)bh * S_LEN + kt + row) * DK + ci * 8);
            cp16(smb + AOFF_VH + dst, Vth + ((size_t)bh * DK + row) * S_LEN + kt + ci * 8);
            cp16(smb + AOFF_VL + dst, Vtl + ((size_t)bh * DK + row) * S_LEN + kt + ci * 8);
        }
        CP_COMMIT();
    };
    load_kv(0, 0);

    // mask row -> smem (plain loads)
    int* msks = (int*)(smem + AOFF_MSK);
#pragma unroll
    for (int p = 0; p < 2; ++p) {
        const int i = tid + p * 256;          // 0..511
        *(int4*)&msks[i * 4] = *(const int4*)&mask[(size_t)bb * S_LEN + i * 4];
    }

    uint32_t qfh[4][4], qfl[4][4];
    float o[8][4];
#pragma unroll
    for (int nj = 0; nj < 8; ++nj)
#pragma unroll
        for (int j = 0; j < 4; ++j) o[nj][j] = 0.f;
    float m0 = -INFINITY, m1 = -INFINITY, l0 = 0.f, l1 = 0.f;

    const int NIT = S_LEN / 64;
    for (int it = 0; it < NIT; ++it) {
        const int kt = it * 64;
        const int buf = it & 1;
        if (it + 1 < NIT) {
            load_kv(kt + 64, buf ^ 1);
            CP_WAIT(1);
        } else {
            CP_WAIT(0);
        }
        __syncthreads();

        if (it == 0) {
            // read persistent Q fragments
#pragma unroll
            for (int k = 0; k < 4; ++k) {
                const uint32_t base = (uint32_t)(wq0 + r) * RSTR + k * 32 + cg * 4;
                qfh[k][0] = *(const uint32_t*)(smem + AOFF_QH + base);
                qfh[k][1] = *(const uint32_t*)(smem + AOFF_QH + base + 8 * RSTR);
                qfh[k][2] = *(const uint32_t*)(smem + AOFF_QH + base + 16);
                qfh[k][3] = *(const uint32_t*)(smem + AOFF_QH + base + 8 * RSTR + 16);
                qfl[k][0] = *(const uint32_t*)(smem + AOFF_QL + base);
                qfl[k][1] = *(const uint32_t*)(smem + AOFF_QL + base + 8 * RSTR);
                qfl[k][2] = *(const uint32_t*)(smem + AOFF_QL + base + 16);
                qfl[k][3] = *(const uint32_t*)(smem + AOFF_QL + base + 8 * RSTR + 16);
            }
        }

        // ---- S = Q K^T ----
        float s[8][4];
#pragma unroll
        for (int nj = 0; nj < 8; ++nj)
#pragma unroll
            for (int j = 0; j < 4; ++j) s[nj][j] = 0.f;

#pragma unroll
        for (int k = 0; k < 4; ++k)
#pragma unroll
            for (int nj = 0; nj < 8; ++nj) {
                const uint32_t kb = (uint32_t)(nj * 8 + r) * RSTR + k * 32 + cg * 4 + buf * 9216;
                uint32_t bh2[2], bl2[2];
                bh2[0] = *(const uint32_t*)(smem + AOFF_KH + kb);
                bh2[1] = *(const uint32_t*)(smem + AOFF_KH + kb + 16);
                bl2[0] = *(const uint32_t*)(smem + AOFF_KL + kb);
                bl2[1] = *(const uint32_t*)(smem + AOFF_KL + kb + 16);
                mma_bf16(s[nj], qfh[k], bh2);
                mma_bf16(s[nj], qfh[k], bl2);
                mma_bf16(s[nj], qfl[k], bh2);
            }

        // ---- mask + scale + online softmax ----
        float mx0 = -INFINITY, mx1 = -INFINITY;
#pragma unroll
        for (int nj = 0; nj < 8; ++nj) {
            const int kc = kt + nj * 8 + cg * 2;
            const bool a0 = msks[kc] != 0;
            const bool a1 = msks[kc + 1] != 0;
            s[nj][0] = a0 ? s[nj][0] * 0.125f : -1e9f;
            s[nj][1] = a1 ? s[nj][1] * 0.125f : -1e9f;
            s[nj][2] = a0 ? s[nj][2] * 0.125f : -1e9f;
            s[nj][3] = a1 ? s[nj][3] * 0.125f : -1e9f;
            mx0 = fmaxf(mx0, fmaxf(s[nj][0], s[nj][1]));
            mx1 = fmaxf(mx1, fmaxf(s[nj][2], s[nj][3]));
        }
        mx0 = fmaxf(mx0, __shfl_xor_sync(0xffffffffu, mx0, 1));
        mx0 = fmaxf(mx0, __shfl_xor_sync(0xffffffffu, mx0, 2));
        mx1 = fmaxf(mx1, __shfl_xor_sync(0xffffffffu, mx1, 1));
        mx1 = fmaxf(mx1, __shfl_xor_sync(0xffffffffu, mx1, 2));

        const float nm0 = fmaxf(m0, mx0);
        const float nm1 = fmaxf(m1, mx1);
        const float f0 = __expf(m0 - nm0);
        const float f1 = __expf(m1 - nm1);
        m0 = nm0; m1 = nm1;

        uint32_t ph[4][4], pl[4][4];
        float la0 = 0.f, la1 = 0.f;
#pragma unroll
        for (int nj = 0; nj < 8; ++nj) {
            const float p0 = __expf(s[nj][0] - m0);
            const float p1 = __expf(s[nj][1] - m0);
            const float p2 = __expf(s[nj][2] - m1);
            const float p3 = __expf(s[nj][3] - m1);
            la0 += p0 + p1;
            la1 += p2 + p3;
            const float h0 = __bfloat162float(__float2bfloat16(p0));
            const float h1 = __bfloat162float(__float2bfloat16(p1));
            const float h2 = __bfloat162float(__float2bfloat16(p2));
            const float h3 = __bfloat162float(__float2bfloat16(p3));
            const int t = nj >> 1;
            if ((nj & 1) == 0) {
                ph[t][0] = packbf(p0, p1);
                ph[t][1] = packbf(p2, p3);
                pl[t][0] = packbf(p0 - h0, p1 - h1);
                pl[t][1] = packbf(p2 - h2, p3 - h3);
            } else {
                ph[t][2] = packbf(p0, p1);
                ph[t][3] = packbf(p2, p3);
                pl[t][2] = packbf(p0 - h0, p1 - h1);
                pl[t][3] = packbf(p2 - h2, p3 - h3);
            }
        }
        la0 += __shfl_xor_sync(0xffffffffu, la0, 1);
        la0 += __shfl_xor_sync(0xffffffffu, la0, 2);
        la1 += __shfl_xor_sync(0xffffffffu, la1, 1);
        la1 += __shfl_xor_sync(0xffffffffu, la1, 2);
        l0 = l0 * f0 + la0;
        l1 = l1 * f1 + la1;

#pragma unroll
        for (int nj = 0; nj < 8; ++nj) {
            o[nj][0] *= f0; o[nj][1] *= f0;
            o[nj][2] *= f1; o[nj][3] *= f1;
        }

        // ---- O += P V  (V^T tiles: B frag n=d, k=key) ----
#pragma unroll
        for (int t = 0; t < 4; ++t)
#pragma unroll
            for (int nj = 0; nj < 8; ++nj) {
                const uint32_t vb = (uint32_t)(nj * 8 + r) * RSTR + t * 32 + cg * 4 + buf * 9216;
                uint32_t bh2[2], bl2[2];
                bh2[0] = *(const uint32_t*)(smem + AOFF_VH + vb);
                bh2[1] = *(const uint32_t*)(smem + AOFF_VH + vb + 16);
                bl2[0] = *(const uint32_t*)(smem + AOFF_VL + vb);
                bl2[1] = *(const uint32_t*)(smem + AOFF_VL + vb + 16);
                mma_bf16(o[nj], ph[t], bh2);
                mma_bf16(o[nj], ph[t], bl2);
                mma_bf16(o[nj], pl[t], bh2);
            }
        __syncthreads();
    }

    // ---- epilogue: normalize, hi/lo split, write om ----
    const float inv0 = 1.f / l0;
    const float inv1 = 1.f / l1;
    const int s0r = q0 + wq0 + r;
    const int s1r = s0r + 8;
#pragma unroll
    for (int nj = 0; nj < 8; ++nj) {
        const int col = hh * 64 + nj * 8 + cg * 2;
        float x0 = o[nj][0] * inv0, y0 = o[nj][1] * inv0;
        float x1 = o[nj][2] * inv1, y1 = o[nj][3] * inv1;
        const size_t a0 = ((size_t)(bb * S_LEN + s0r)) * DM + col;
        const size_t a1 = ((size_t)(bb * S_LEN + s1r)) * DM + col;
        float hx = __bfloat162float(__float2bfloat16(x0));
        float hy = __bfloat162float(__float2bfloat16(y0));
        *(uint32_t*)&omh[a0] = packbf(x0, y0);
        *(uint32_t*)&oml[a0] = packbf(x0 - hx, y0 - hy);
        hx = __bfloat162float(__float2bfloat16(x1));
        hy = __bfloat162float(__float2bfloat16(y1));
        *(uint32_t*)&omh[a1] = packbf(x1, y1);
        *(uint32_t*)&oml[a1] = packbf(x1 - hx, y1 - hy);
    }
}

// ---------------- launch ----------------
extern "C" void kernel_launch(void* const* d_in, const int* in_sizes, int n_in,
                              void* d_out, int out_size) {
    const float* q  = (const float*)d_in[0];
    const float* k  = (const float*)d_in[1];
    const float* v  = (const float*)d_in[2];
    const int*   mk = (const int*)  d_in[3];
    const float* wq = (const float*)d_in[4];
    const float* bq = (const float*)d_in[5];
    const float* wk = (const float*)d_in[6];
    const float* bk = (const float*)d_in[7];
    const float* wv = (const float*)d_in[8];
    const float* bv = (const float*)d_in[9];
    const float* wo = (const float*)d_in[10];
    const float* bo = (const float*)d_in[11];
    float* out = (float*)d_out;

    __nv_bfloat16 *xh, *xl, *wh, *wl, *qhh, *qhl, *khh, *khl, *vth, *vtl, *omh, *oml;
    cudaGetSymbolAddress((void**)&xh, g_xh);
    cudaGetSymbolAddress((void**)&xl, g_xl);
    cudaGetSymbolAddress((void**)&wh, g_wh);
    cudaGetSymbolAddress((void**)&wl, g_wl);
    cudaGetSymbolAddress((void**)&qhh, g_qhh);
    cudaGetSymbolAddress((void**)&qhl, g_qhl);
    cudaGetSymbolAddress((void**)&khh, g_khh);
    cudaGetSymbolAddress((void**)&khl, g_khl);
    cudaGetSymbolAddress((void**)&vth, g_vth);
    cudaGetSymbolAddress((void**)&vtl, g_vtl);
    cudaGetSymbolAddress((void**)&omh, g_omh);
    cudaGetSymbolAddress((void**)&oml, g_oml);

    cudaFuncSetAttribute(gemm_mma<0>, cudaFuncAttributeMaxDynamicSharedMemorySize, GSMEM);
    cudaFuncSetAttribute(gemm_mma<1>, cudaFuncAttributeMaxDynamicSharedMemorySize, GSMEM);
    cudaFuncSetAttribute(gemm_mma<2>, cudaFuncAttributeMaxDynamicSharedMemorySize, GSMEM);
    cudaFuncSetAttribute(attn_mma, cudaFuncAttributeMaxDynamicSharedMemorySize, ASMEM);

    const int nx4 = MTOT * DM / 4;
    const int nw4 = DM * DM / 4;
    dim3 gg(DM / 128, MTOT / 128);

    // Q projection
    split_k<<<(nx4 + 255) / 256, 256>>>(q, xh, xl, nx4);
    split_k<<<(nw4 + 255) / 256, 256>>>(wq, wh, wl, nw4);
    gemm_mma<1><<<gg, 256, GSMEM>>>(xh, xl, wh, wl, bq, nullptr, qhh, qhl);
    // K projection
    split_k<<<(nx4 + 255) / 256, 256>>>(k, xh, xl, nx4);
    split_k<<<(nw4 + 255) / 256, 256>>>(wk, wh, wl, nw4);
    gemm_mma<1><<<gg, 256, GSMEM>>>(xh, xl, wh, wl, bk, nullptr, khh, khl);
    // V projection (transposed per-head output)
    split_k<<<(nx4 + 255) / 256, 256>>>(v, xh, xl, nx4);
    split_k<<<(nw4 + 255) / 256, 256>>>(wv, wh, wl, nw4);
    gemm_mma<2><<<gg, 256, GSMEM>>>(xh, xl, wh, wl, bv, nullptr, vth, vtl);

    // attention (outputs bf16 hi/lo om directly)
    dim3 ga(S_LEN / 128, B_SZ * NH);
    attn_mma<<<ga, 256, ASMEM>>>(qhh, qhl, khh, khl, vth, vtl, mk, omh, oml);

    // output projection
    split_k<<<(nw4 + 255) / 256, 256>>>(wo, wh, wl, nw4);
    gemm_mma<0><<<gg, 256, GSMEM>>>(omh, oml, wh, wl, bo, out, nullptr, nullptr);
}

// round 5
// speedup vs baseline: 3.4545x; 1.3374x over previous
#include <cuda_runtime.h>
#include <cuda_fp16.h>
#include <math.h>
#include <cstdint>

#define B_SZ  4
#define S_LEN 2048
#define DM    1024
#define NH    16
#define DK    64
#define MTOT  (B_SZ * S_LEN)   // 8192

// ---------------- scratch (device globals) ----------------
__device__ __half g_xa[(size_t)MTOT * DM];          // truncated activations
__device__ __half g_wh[(size_t)DM * DM];            // weight hi
__device__ __half g_wl[(size_t)DM * DM];            // weight lo
__device__ __half g_q[(size_t)B_SZ * NH * S_LEN * DK];
__device__ __half g_kh[(size_t)B_SZ * NH * S_LEN * DK];
__device__ __half g_kl[(size_t)B_SZ * NH * S_LEN * DK];
__device__ __half g_vh[(size_t)B_SZ * NH * DK * S_LEN];   // V^T hi
__device__ __half g_vl[(size_t)B_SZ * NH * DK * S_LEN];   // V^T lo
__device__ __half g_om[(size_t)MTOT * DM];          // attention output (f16)

// ---------------- helpers ----------------
__device__ __forceinline__ uint32_t smem_u32(const void* p) {
    uint32_t a;
    asm("{ .reg .u64 t; cvta.to.shared.u64 t, %1; cvt.u32.u64 %0, t; }" : "=r"(a) : "l"(p));
    return a;
}
__device__ __forceinline__ void cp16(uint32_t dst, const void* src) {
    asm volatile("cp.async.cg.shared.global [%0], [%1], 16;" :: "r"(dst), "l"(src) : "memory");
}
#define CP_COMMIT() asm volatile("cp.async.commit_group;" ::: "memory")
#define CP_WAIT(n)  asm volatile("cp.async.wait_group %0;" :: "n"(n) : "memory")

__device__ __forceinline__ void mma_f16(float* d, const uint32_t* a, const uint32_t* b) {
    asm volatile(
        "mma.sync.aligned.m16n8k16.row.col.f32.f16.f16.f32 "
        "{%0,%1,%2,%3}, {%4,%5,%6,%7}, {%8,%9}, {%0,%1,%2,%3};"
        : "+f"(d[0]), "+f"(d[1]), "+f"(d[2]), "+f"(d[3])
        : "r"(a[0]), "r"(a[1]), "r"(a[2]), "r"(a[3]), "r"(b[0]), "r"(b[1]));
}
__device__ __forceinline__ uint32_t packh(float a, float b) {
    __half2 t = __floats2half2_rn(a, b);
    return *(uint32_t*)&t;
}

// ---------------- fp32 -> fp16 truncation / hi-lo split ----------------
__global__ void __launch_bounds__(256) trunc_x(const float* __restrict__ x,
                                               __half* __restrict__ o, int n4)
{
    int i = blockIdx.x * 256 + threadIdx.x;
    if (i >= n4) return;
    float4 v = ((const float4*)x)[i];
    ((__half2*)o)[i * 2 + 0] = __floats2half2_rn(v.x, v.y);
    ((__half2*)o)[i * 2 + 1] = __floats2half2_rn(v.z, v.w);
}

__global__ void __launch_bounds__(256) split_w(const float* __restrict__ x,
                                               __half* __restrict__ hi,
                                               __half* __restrict__ lo, int n4)
{
    int i = blockIdx.x * 256 + threadIdx.x;
    if (i >= n4) return;
    float4 v = ((const float4*)x)[i];
    __half h0 = __float2half_rn(v.x);
    __half h1 = __float2half_rn(v.y);
    __half h2 = __float2half_rn(v.z);
    __half h3 = __float2half_rn(v.w);
    ((__half2*)hi)[i * 2 + 0] = __half2(h0, h1);
    ((__half2*)hi)[i * 2 + 1] = __half2(h2, h3);
    ((__half2*)lo)[i * 2 + 0] = __floats2half2_rn(v.x - __half2float(h0), v.y - __half2float(h1));
    ((__half2*)lo)[i * 2 + 1] = __floats2half2_rn(v.z - __half2float(h2), v.w - __half2float(h3));
}

// ---------------- fp16x2 mma.sync GEMM ----------------
// C[m][n] = sum_k A[m][k]*(Bh+Bl)[n][k] + bias[n]
// EPI: 0 = fp32 row-major; 1 = head-split f16 (Q); 2 = head-split f16 hi/lo (K);
//      3 = transposed [bh][d][s] f16 hi/lo (V^T)
#define BK        32
#define NCHUNK    (DM / BK)
#define ASTRIDE_B 80
#define TILE_B    (128 * ASTRIDE_B)
#define GSMEM     (2 * 3 * TILE_B)      // 61440

template<int EPI>
__global__ void __launch_bounds__(256, 1) gemm_mma(const __half* __restrict__ A,
                                                   const __half* __restrict__ Bh,
                                                   const __half* __restrict__ Bl,
                                                   const float* __restrict__ bias,
                                                   float* __restrict__ out,
                                                   __half* __restrict__ oh,
                                                   __half* __restrict__ ol)
{
    extern __shared__ char smem[];
    const uint32_t smb = smem_u32(smem);
    const int tid = threadIdx.x;
    const int w   = tid >> 5;
    const int l   = tid & 31;
    const int m0  = blockIdx.y * 128;
    const int n0  = blockIdx.x * 128;
    const int wm  = (w & 1) * 64;
    const int wn  = (w >> 1) * 32;

    const int i0 = tid, i1 = tid + 256;
    const int r0 = i0 >> 2, c0 = i0 & 3;
    const int r1 = i1 >> 2, c1 = i1 & 3;

    auto buf_off = [](int buf, int t) -> uint32_t {
        return (uint32_t)(buf * 3 + t) * TILE_B;
    };

    auto load_chunk = [&](int ck, int buf) {
        const size_t ko = (size_t)ck * BK;
        const uint32_t s0 = (uint32_t)r0 * ASTRIDE_B + c0 * 16;
        const uint32_t s1 = (uint32_t)r1 * ASTRIDE_B + c1 * 16;
        cp16(smb + buf_off(buf, 0) + s0, A  + (size_t)(m0 + r0) * DM + ko + c0 * 8);
        cp16(smb + buf_off(buf, 0) + s1, A  + (size_t)(m0 + r1) * DM + ko + c1 * 8);
        cp16(smb + buf_off(buf, 1) + s0, Bh + (size_t)(n0 + r0) * DM + ko + c0 * 8);
        cp16(smb + buf_off(buf, 1) + s1, Bh + (size_t)(n0 + r1) * DM + ko + c1 * 8);
        cp16(smb + buf_off(buf, 2) + s0, Bl + (size_t)(n0 + r0) * DM + ko + c0 * 8);
        cp16(smb + buf_off(buf, 2) + s1, Bl + (size_t)(n0 + r1) * DM + ko + c1 * 8);
        CP_COMMIT();
    };

    float acc[4][4][4];
#pragma unroll
    for (int mi = 0; mi < 4; ++mi)
#pragma unroll
        for (int ni = 0; ni < 4; ++ni)
#pragma unroll
            for (int j = 0; j < 4; ++j) acc[mi][ni][j] = 0.f;

    load_chunk(0, 0);

    const int lr = l >> 2;
    const int lc = (l & 3) * 4;

    for (int ck = 0; ck < NCHUNK; ++ck) {
        const int buf = ck & 1;
        if (ck + 1 < NCHUNK) {
            load_chunk(ck + 1, buf ^ 1);
            CP_WAIT(1);
        } else {
            CP_WAIT(0);
        }
        __syncthreads();

        const char* sA  = smem + buf_off(buf, 0);
        const char* sBh = smem + buf_off(buf, 1);
        const char* sBl = smem + buf_off(buf, 2);

#pragma unroll
        for (int kk = 0; kk < BK; kk += 16) {
            uint32_t af[4][4], bfh[4][2], bfl[4][2];
#pragma unroll
            for (int mi = 0; mi < 4; ++mi) {
                const uint32_t base = (uint32_t)(wm + mi * 16 + lr) * ASTRIDE_B + kk * 2 + lc;
                af[mi][0] = *(const uint32_t*)(sA + base);
                af[mi][1] = *(const uint32_t*)(sA + base + 8 * ASTRIDE_B);
                af[mi][2] = *(const uint32_t*)(sA + base + 16);
                af[mi][3] = *(const uint32_t*)(sA + base + 8 * ASTRIDE_B + 16);
            }
#pragma unroll
            for (int ni = 0; ni < 4; ++ni) {
                const uint32_t base = (uint32_t)(wn + ni * 8 + lr) * ASTRIDE_B + kk * 2 + lc;
                bfh[ni][0] = *(const uint32_t*)(sBh + base);
                bfh[ni][1] = *(const uint32_t*)(sBh + base + 16);
                bfl[ni][0] = *(const uint32_t*)(sBl + base);
                bfl[ni][1] = *(const uint32_t*)(sBl + base + 16);
            }
#pragma unroll
            for (int mi = 0; mi < 4; ++mi)
#pragma unroll
                for (int ni = 0; ni < 4; ++ni) {
                    mma_f16(acc[mi][ni], af[mi], bfh[ni]);
                    mma_f16(acc[mi][ni], af[mi], bfl[ni]);
                }
        }
        __syncthreads();
    }

#pragma unroll
    for (int mi = 0; mi < 4; ++mi) {
        const int mrow = m0 + wm + mi * 16 + lr;
        const int b = mrow >> 11;
        const int s = mrow & (S_LEN - 1);
#pragma unroll
        for (int ni = 0; ni < 4; ++ni) {
            const int col = n0 + wn + ni * 8 + (l & 3) * 2;
            const float2 b2 = *(const float2*)&bias[col];
            float2 v0 = { acc[mi][ni][0] + b2.x, acc[mi][ni][1] + b2.y };
            float2 v1 = { acc[mi][ni][2] + b2.x, acc[mi][ni][3] + b2.y };
            if (EPI == 0) {
                *(float2*)&out[(size_t)mrow * DM + col] = v0;
                *(float2*)&out[(size_t)(mrow + 8) * DM + col] = v1;
            } else if (EPI == 1) {
                const int hd = col >> 6, d = col & 63;
                const size_t base = ((size_t)(b * NH + hd) * S_LEN + s) * DK + d;
                *(uint32_t*)&oh[base] = packh(v0.x, v0.y);
                *(uint32_t*)&oh[base + 8 * DK] = packh(v1.x, v1.y);
            } else if (EPI == 2) {
                const int hd = col >> 6, d = col & 63;
                const size_t base = ((size_t)(b * NH + hd) * S_LEN + s) * DK + d;
                float hx = __half2float(__float2half_rn(v0.x));
                float hy = __half2float(__float2half_rn(v0.y));
                *(uint32_t*)&oh[base] = packh(v0.x, v0.y);
                *(uint32_t*)&ol[base] = packh(v0.x - hx, v0.y - hy);
                hx = __half2float(__float2half_rn(v1.x));
                hy = __half2float(__float2half_rn(v1.y));
                *(uint32_t*)&oh[base + 8 * DK] = packh(v1.x, v1.y);
                *(uint32_t*)&ol[base + 8 * DK] = packh(v1.x - hx, v1.y - hy);
            } else {
                const int hd = col >> 6, d = col & 63;
                const size_t rb = ((size_t)(b * NH + hd) * DK + d) * S_LEN;
                float h;
                h = __half2float(__float2half_rn(v0.x));
                oh[rb + s] = __float2half_rn(v0.x);
                ol[rb + s] = __float2half_rn(v0.x - h);
                h = __half2float(__float2half_rn(v0.y));
                oh[rb + S_LEN + s] = __float2half_rn(v0.y);
                ol[rb + S_LEN + s] = __float2half_rn(v0.y - h);
                h = __half2float(__float2half_rn(v1.x));
                oh[rb + s + 8] = __float2half_rn(v1.x);
                ol[rb + s + 8] = __float2half_rn(v1.x - h);
                h = __half2float(__float2half_rn(v1.y));
                oh[rb + S_LEN + s + 8] = __float2half_rn(v1.y);
                ol[rb + S_LEN + s + 8] = __float2half_rn(v1.y - h);
            }
        }
    }
}

// ---------------- fp16x2 mma.sync flash attention ----------------
// grid (S/128, B*H), 256 threads. Q truncated f16; K, V^T hi/lo f16.
#define RSTR      144
#define AOFF_Q    0                 // 128*144 = 18432
#define AOFF_KH   18432             // 2 bufs x 9216
#define AOFF_KL   36864
#define AOFF_VH   55296
#define AOFF_VL   73728
#define AOFF_MSK  92160
#define ASMEM     100352

__global__ void __launch_bounds__(256, 1) attn_mma(const __half* __restrict__ Q,
                                                   const __half* __restrict__ Kh,
                                                   const __half* __restrict__ Kl,
                                                   const __half* __restrict__ Vh,
                                                   const __half* __restrict__ Vl,
                                                   const int* __restrict__ mask,
                                                   __half* __restrict__ om)
{
    extern __shared__ char smem[];
    const uint32_t smb = smem_u32(smem);
    const int tid = threadIdx.x;
    const int w   = tid >> 5;
    const int l   = tid & 31;
    const int bh  = blockIdx.y;
    const int bb  = bh >> 4;
    const int hh  = bh & 15;
    const int q0  = blockIdx.x * 128;
    const int wq0 = w * 16;
    const int r   = l >> 2;
    const int cg  = l & 3;

    // Q tile (single f16)
#pragma unroll
    for (int p = 0; p < 4; ++p) {
        const int idx = tid + p * 256;
        const int row = idx >> 3, ci = idx & 7;
        cp16(smb + AOFF_Q + row * RSTR + ci * 16,
             Q + ((size_t)bh * S_LEN + q0 + row) * DK + ci * 8);
    }

    auto load_kv = [&](int kt, int buf) {
#pragma unroll
        for (int p = 0; p < 2; ++p) {
            const int idx = tid + p * 256;
            const int row = idx >> 3, ci = idx & 7;
            const uint32_t dst = (uint32_t)row * RSTR + ci * 16 + buf * 9216;
            cp16(smb + AOFF_KH + dst, Kh + ((size_t)bh * S_LEN + kt + row) * DK + ci * 8);
            cp16(smb + AOFF_KL + dst, Kl + ((size_t)bh * S_LEN + kt + row) * DK + ci * 8);
            cp16(smb + AOFF_VH + dst, Vh + ((size_t)bh * DK + row) * S_LEN + kt + ci * 8);
            cp16(smb + AOFF_VL + dst, Vl + ((size_t)bh * DK + row) * S_LEN + kt + ci * 8);
        }
        CP_COMMIT();
    };
    load_kv(0, 0);

    int* msks = (int*)(smem + AOFF_MSK);
#pragma unroll
    for (int p = 0; p < 2; ++p) {
        const int i = tid + p * 256;
        *(int4*)&msks[i * 4] = *(const int4*)&mask[(size_t)bb * S_LEN + i * 4];
    }

    uint32_t qf[4][4];
    float o[8][4];
#pragma unroll
    for (int nj = 0; nj < 8; ++nj)
#pragma unroll
        for (int j = 0; j < 4; ++j) o[nj][j] = 0.f;
    float m0 = -INFINITY, m1 = -INFINITY, l0 = 0.f, l1 = 0.f;

    const int NIT = S_LEN / 64;
    for (int it = 0; it < NIT; ++it) {
        const int kt = it * 64;
        const int buf = it & 1;
        if (it + 1 < NIT) {
            load_kv(kt + 64, buf ^ 1);
            CP_WAIT(1);
        } else {
            CP_WAIT(0);
        }
        __syncthreads();

        if (it == 0) {
#pragma unroll
            for (int k = 0; k < 4; ++k) {
                const uint32_t base = (uint32_t)(wq0 + r) * RSTR + k * 32 + cg * 4;
                qf[k][0] = *(const uint32_t*)(smem + AOFF_Q + base);
                qf[k][1] = *(const uint32_t*)(smem + AOFF_Q + base + 8 * RSTR);
                qf[k][2] = *(const uint32_t*)(smem + AOFF_Q + base + 16);
                qf[k][3] = *(const uint32_t*)(smem + AOFF_Q + base + 8 * RSTR + 16);
            }
        }

        // ---- S = Q K^T ----
        float s[8][4];
#pragma unroll
        for (int nj = 0; nj < 8; ++nj)
#pragma unroll
            for (int j = 0; j < 4; ++j) s[nj][j] = 0.f;

#pragma unroll
        for (int k = 0; k < 4; ++k)
#pragma unroll
            for (int nj = 0; nj < 8; ++nj) {
                const uint32_t kb = (uint32_t)(nj * 8 + r) * RSTR + k * 32 + cg * 4 + buf * 9216;
                uint32_t bh2[2], bl2[2];
                bh2[0] = *(const uint32_t*)(smem + AOFF_KH + kb);
                bh2[1] = *(const uint32_t*)(smem + AOFF_KH + kb + 16);
                bl2[0] = *(const uint32_t*)(smem + AOFF_KL + kb);
                bl2[1] = *(const uint32_t*)(smem + AOFF_KL + kb + 16);
                mma_f16(s[nj], qf[k], bh2);
                mma_f16(s[nj], qf[k], bl2);
            }

        // ---- mask + scale + online softmax ----
        float mx0 = -INFINITY, mx1 = -INFINITY;
#pragma unroll
        for (int nj = 0; nj < 8; ++nj) {
            const int kc = kt + nj * 8 + cg * 2;
            const bool a0 = msks[kc] != 0;
            const bool a1 = msks[kc + 1] != 0;
            s[nj][0] = a0 ? s[nj][0] * 0.125f : -1e9f;
            s[nj][1] = a1 ? s[nj][1] * 0.125f : -1e9f;
            s[nj][2] = a0 ? s[nj][2] * 0.125f : -1e9f;
            s[nj][3] = a1 ? s[nj][3] * 0.125f : -1e9f;
            mx0 = fmaxf(mx0, fmaxf(s[nj][0], s[nj][1]));
            mx1 = fmaxf(mx1, fmaxf(s[nj][2], s[nj][3]));
        }
        mx0 = fmaxf(mx0, __shfl_xor_sync(0xffffffffu, mx0, 1));
        mx0 = fmaxf(mx0, __shfl_xor_sync(0xffffffffu, mx0, 2));
        mx1 = fmaxf(mx1, __shfl_xor_sync(0xffffffffu, mx1, 1));
        mx1 = fmaxf(mx1, __shfl_xor_sync(0xffffffffu, mx1, 2));

        const float nm0 = fmaxf(m0, mx0);
        const float nm1 = fmaxf(m1, mx1);
        const float f0 = __expf(m0 - nm0);
        const float f1 = __expf(m1 - nm1);
        m0 = nm0; m1 = nm1;

        uint32_t ph[4][4];
        float la0 = 0.f, la1 = 0.f;
#pragma unroll
        for (int nj = 0; nj < 8; ++nj) {
            const float p0 = __expf(s[nj][0] - m0);
            const float p1 = __expf(s[nj][1] - m0);
            const float p2 = __expf(s[nj][2] - m1);
            const float p3 = __expf(s[nj][3] - m1);
            la0 += p0 + p1;
            la1 += p2 + p3;
            const int t = nj >> 1;
            if ((nj & 1) == 0) {
                ph[t][0] = packh(p0, p1);
                ph[t][1] = packh(p2, p3);
            } else {
                ph[t][2] = packh(p0, p1);
                ph[t][3] = packh(p2, p3);
            }
        }
        la0 += __shfl_xor_sync(0xffffffffu, la0, 1);
        la0 += __shfl_xor_sync(0xffffffffu, la0, 2);
        la1 += __shfl_xor_sync(0xffffffffu, la1, 1);
        la1 += __shfl_xor_sync(0xffffffffu, la1, 2);
        l0 = l0 * f0 + la0;
        l1 = l1 * f1 + la1;

#pragma unroll
        for (int nj = 0; nj < 8; ++nj) {
            o[nj][0] *= f0; o[nj][1] *= f0;
            o[nj][2] *= f1; o[nj][3] *= f1;
        }

        // ---- O += P V ----
#pragma unroll
        for (int t = 0; t < 4; ++t)
#pragma unroll
            for (int nj = 0; nj < 8; ++nj) {
                const uint32_t vb = (uint32_t)(nj * 8 + r) * RSTR + t * 32 + cg * 4 + buf * 9216;
                uint32_t bh2[2], bl2[2];
                bh2[0] = *(const uint32_t*)(smem + AOFF_VH + vb);
                bh2[1] = *(const uint32_t*)(smem + AOFF_VH + vb + 16);
                bl2[0] = *(const uint32_t*)(smem + AOFF_VL + vb);
                bl2[1] = *(const uint32_t*)(smem + AOFF_VL + vb + 16);
                mma_f16(o[nj], ph[t], bh2);
                mma_f16(o[nj], ph[t], bl2);
            }
        __syncthreads();
    }

    // ---- epilogue: normalize, write f16 om ----
    const float inv0 = 1.f / l0;
    const float inv1 = 1.f / l1;
    const int s0r = q0 + wq0 + r;
    const int s1r = s0r + 8;
#pragma unroll
    for (int nj = 0; nj < 8; ++nj) {
        const int col = hh * 64 + nj * 8 + cg * 2;
        float x0 = o[nj][0] * inv0, y0 = o[nj][1] * inv0;
        float x1 = o[nj][2] * inv1, y1 = o[nj][3] * inv1;
        *(uint32_t*)&om[((size_t)(bb * S_LEN + s0r)) * DM + col] = packh(x0, y0);
        *(uint32_t*)&om[((size_t)(bb * S_LEN + s1r)) * DM + col] = packh(x1, y1);
    }
}

// ---------------- launch ----------------
extern "C" void kernel_launch(void* const* d_in, const int* in_sizes, int n_in,
                              void* d_out, int out_size) {
    const float* q  = (const float*)d_in[0];
    const float* k  = (const float*)d_in[1];
    const float* v  = (const float*)d_in[2];
    const int*   mk = (const int*)  d_in[3];
    const float* wq = (const float*)d_in[4];
    const float* bq = (const float*)d_in[5];
    const float* wk = (const float*)d_in[6];
    const float* bk = (const float*)d_in[7];
    const float* wv = (const float*)d_in[8];
    const float* bv = (const float*)d_in[9];
    const float* wo = (const float*)d_in[10];
    const float* bo = (const float*)d_in[11];
    float* out = (float*)d_out;

    __half *xa, *wh, *wl, *qf, *kh, *kl, *vh, *vl, *om;
    cudaGetSymbolAddress((void**)&xa, g_xa);
    cudaGetSymbolAddress((void**)&wh, g_wh);
    cudaGetSymbolAddress((void**)&wl, g_wl);
    cudaGetSymbolAddress((void**)&qf, g_q);
    cudaGetSymbolAddress((void**)&kh, g_kh);
    cudaGetSymbolAddress((void**)&kl, g_kl);
    cudaGetSymbolAddress((void**)&vh, g_vh);
    cudaGetSymbolAddress((void**)&vl, g_vl);
    cudaGetSymbolAddress((void**)&om, g_om);

    cudaFuncSetAttribute(gemm_mma<0>, cudaFuncAttributeMaxDynamicSharedMemorySize, GSMEM);
    cudaFuncSetAttribute(gemm_mma<1>, cudaFuncAttributeMaxDynamicSharedMemorySize, GSMEM);
    cudaFuncSetAttribute(gemm_mma<2>, cudaFuncAttributeMaxDynamicSharedMemorySize, GSMEM);
    cudaFuncSetAttribute(gemm_mma<3>, cudaFuncAttributeMaxDynamicSharedMemorySize, GSMEM);
    cudaFuncSetAttribute(attn_mma, cudaFuncAttributeMaxDynamicSharedMemorySize, ASMEM);

    const int nx4 = MTOT * DM / 4;
    const int nw4 = DM * DM / 4;
    dim3 gg(DM / 128, MTOT / 128);

    // Q projection
    trunc_x<<<(nx4 + 255) / 256, 256>>>(q, xa, nx4);
    split_w<<<(nw4 + 255) / 256, 256>>>(wq, wh, wl, nw4);
    gemm_mma<1><<<gg, 256, GSMEM>>>(xa, wh, wl, bq, nullptr, qf, nullptr);
    // K projection (hi/lo output)
    trunc_x<<<(nx4 + 255) / 256, 256>>>(k, xa, nx4);
    split_w<<<(nw4 + 255) / 256, 256>>>(wk, wh, wl, nw4);
    gemm_mma<2><<<gg, 256, GSMEM>>>(xa, wh, wl, bk, nullptr, kh, kl);
    // V projection (transposed hi/lo output)
    trunc_x<<<(nx4 + 255) / 256, 256>>>(v, xa, nx4);
    split_w<<<(nw4 + 255) / 256, 256>>>(wv, wh, wl, nw4);
    gemm_mma<3><<<gg, 256, GSMEM>>>(xa, wh, wl, bv, nullptr, vh, vl);

    // attention
    dim3 ga(S_LEN / 128, B_SZ * NH);
    attn_mma<<<ga, 256, ASMEM>>>(qf, kh, kl, vh, vl, mk, om);

    // output projection
    split_w<<<(nw4 + 255) / 256, 256>>>(wo, wh, wl, nw4);
    gemm_mma<0><<<gg, 256, GSMEM>>>(om, wh, wl, bo, out, nullptr, nullptr);
}

// round 6
// speedup vs baseline: 3.5336x; 1.0229x over previous
#include <cuda_runtime.h>
#include <cuda_fp16.h>
#include <math.h>
#include <cstdint>

#define B_SZ  4
#define S_LEN 2048
#define DM    1024
#define NH    16
#define DK    64
#define MTOT  (B_SZ * S_LEN)   // 8192

// ---------------- scratch (device globals) ----------------
__device__ __half g_xa[(size_t)MTOT * DM];
__device__ __half g_wh[(size_t)DM * DM];
__device__ __half g_wl[(size_t)DM * DM];
__device__ __half g_q[(size_t)B_SZ * NH * S_LEN * DK];
__device__ __half g_kh[(size_t)B_SZ * NH * S_LEN * DK];
__device__ __half g_kl[(size_t)B_SZ * NH * S_LEN * DK];
__device__ __half g_vh[(size_t)B_SZ * NH * DK * S_LEN];
__device__ __half g_vl[(size_t)B_SZ * NH * DK * S_LEN];
__device__ __half g_om[(size_t)MTOT * DM];

// ---------------- helpers ----------------
__device__ __forceinline__ uint32_t smem_u32(const void* p) {
    uint32_t a;
    asm("{ .reg .u64 t; cvta.to.shared.u64 t, %1; cvt.u32.u64 %0, t; }" : "=r"(a) : "l"(p));
    return a;
}
__device__ __forceinline__ void cp16(uint32_t dst, const void* src) {
    asm volatile("cp.async.cg.shared.global [%0], [%1], 16;" :: "r"(dst), "l"(src) : "memory");
}
#define CP_COMMIT() asm volatile("cp.async.commit_group;" ::: "memory")
#define CP_WAIT(n)  asm volatile("cp.async.wait_group %0;" :: "n"(n) : "memory")

__device__ __forceinline__ void mma_f16(float* d, const uint32_t* a, const uint32_t* b) {
    asm volatile(
        "mma.sync.aligned.m16n8k16.row.col.f32.f16.f16.f32 "
        "{%0,%1,%2,%3}, {%4,%5,%6,%7}, {%8,%9}, {%0,%1,%2,%3};"
        : "+f"(d[0]), "+f"(d[1]), "+f"(d[2]), "+f"(d[3])
        : "r"(a[0]), "r"(a[1]), "r"(a[2]), "r"(a[3]), "r"(b[0]), "r"(b[1]));
}
__device__ __forceinline__ void ldm_x4(uint32_t* r, uint32_t addr) {
    asm volatile("ldmatrix.sync.aligned.m8n8.x4.shared.b16 {%0,%1,%2,%3}, [%4];"
        : "=r"(r[0]), "=r"(r[1]), "=r"(r[2]), "=r"(r[3]) : "r"(addr));
}
__device__ __forceinline__ uint32_t packh(float a, float b) {
    __half2 t = __floats2half2_rn(a, b);
    return *(uint32_t*)&t;
}

// ---------------- fp32 -> fp16 truncation / hi-lo split ----------------
__global__ void __launch_bounds__(256) trunc_x(const float* __restrict__ x,
                                               __half* __restrict__ o, int n4)
{
    int i = blockIdx.x * 256 + threadIdx.x;
    if (i >= n4) return;
    float4 v = ((const float4*)x)[i];
    ((__half2*)o)[i * 2 + 0] = __floats2half2_rn(v.x, v.y);
    ((__half2*)o)[i * 2 + 1] = __floats2half2_rn(v.z, v.w);
}

__global__ void __launch_bounds__(256) split_w(const float* __restrict__ x,
                                               __half* __restrict__ hi,
                                               __half* __restrict__ lo, int n4)
{
    int i = blockIdx.x * 256 + threadIdx.x;
    if (i >= n4) return;
    float4 v = ((const float4*)x)[i];
    __half h0 = __float2half_rn(v.x);
    __half h1 = __float2half_rn(v.y);
    __half h2 = __float2half_rn(v.z);
    __half h3 = __float2half_rn(v.w);
    ((__half2*)hi)[i * 2 + 0] = __half2(h0, h1);
    ((__half2*)hi)[i * 2 + 1] = __half2(h2, h3);
    ((__half2*)lo)[i * 2 + 0] = __floats2half2_rn(v.x - __half2float(h0), v.y - __half2float(h1));
    ((__half2*)lo)[i * 2 + 1] = __floats2half2_rn(v.z - __half2float(h2), v.w - __half2float(h3));
}

// ---------------- fp16x2 mma.sync GEMM (ldmatrix fragments) ----------------
#define BK        32
#define NCHUNK    (DM / BK)
#define ASTRIDE_B 80
#define TILE_B    (128 * ASTRIDE_B)
#define GSMEM     (2 * 3 * TILE_B)

template<int EPI>
__global__ void __launch_bounds__(256, 1) gemm_mma(const __half* __restrict__ A,
                                                   const __half* __restrict__ Bh,
                                                   const __half* __restrict__ Bl,
                                                   const float* __restrict__ bias,
                                                   float* __restrict__ out,
                                                   __half* __restrict__ oh,
                                                   __half* __restrict__ ol)
{
    extern __shared__ char smem[];
    const uint32_t smb = smem_u32(smem);
    const int tid = threadIdx.x;
    const int w   = tid >> 5;
    const int l   = tid & 31;
    const int m0  = blockIdx.y * 128;
    const int n0  = blockIdx.x * 128;
    const int wm  = (w & 1) * 64;
    const int wn  = (w >> 1) * 32;

    const int i0 = tid, i1 = tid + 256;
    const int r0 = i0 >> 2, c0 = i0 & 3;
    const int r1 = i1 >> 2, c1 = i1 & 3;

    auto buf_off = [](int buf, int t) -> uint32_t {
        return (uint32_t)(buf * 3 + t) * TILE_B;
    };

    auto load_chunk = [&](int ck, int buf) {
        const size_t ko = (size_t)ck * BK;
        const uint32_t s0 = (uint32_t)r0 * ASTRIDE_B + c0 * 16;
        const uint32_t s1 = (uint32_t)r1 * ASTRIDE_B + c1 * 16;
        cp16(smb + buf_off(buf, 0) + s0, A  + (size_t)(m0 + r0) * DM + ko + c0 * 8);
        cp16(smb + buf_off(buf, 0) + s1, A  + (size_t)(m0 + r1) * DM + ko + c1 * 8);
        cp16(smb + buf_off(buf, 1) + s0, Bh + (size_t)(n0 + r0) * DM + ko + c0 * 8);
        cp16(smb + buf_off(buf, 1) + s1, Bh + (size_t)(n0 + r1) * DM + ko + c1 * 8);
        cp16(smb + buf_off(buf, 2) + s0, Bl + (size_t)(n0 + r0) * DM + ko + c0 * 8);
        cp16(smb + buf_off(buf, 2) + s1, Bl + (size_t)(n0 + r1) * DM + ko + c1 * 8);
        CP_COMMIT();
    };

    float acc[4][4][4];
#pragma unroll
    for (int mi = 0; mi < 4; ++mi)
#pragma unroll
        for (int ni = 0; ni < 4; ++ni)
#pragma unroll
            for (int j = 0; j < 4; ++j) acc[mi][ni][j] = 0.f;

    load_chunk(0, 0);

    // ldmatrix lane address components
    const int g    = l >> 3;
    const int arow = (g & 1) * 8 + (l & 7);       // A: m0=(m0-7,k0-7) m1=(m+8) m2=(k+8) m3=(m+8,k+8)
    const int acol = (g >> 1) * 16;
    const int brow = (g >> 1) * 8 + (l & 7);      // B: m0=(n0-7,k0-7) m1=(n0-7,k+8) m2=(n+8,..) m3
    const int bcol = (g & 1) * 16;

    for (int ck = 0; ck < NCHUNK; ++ck) {
        const int buf = ck & 1;
        if (ck + 1 < NCHUNK) {
            load_chunk(ck + 1, buf ^ 1);
            CP_WAIT(1);
        } else {
            CP_WAIT(0);
        }
        __syncthreads();

        const uint32_t sA  = smb + buf_off(buf, 0);
        const uint32_t sBh = smb + buf_off(buf, 1);
        const uint32_t sBl = smb + buf_off(buf, 2);

#pragma unroll
        for (int kk = 0; kk < BK; kk += 16) {
            uint32_t af[4][4], bfh[4][2], bfl[4][2];
#pragma unroll
            for (int mi = 0; mi < 4; ++mi)
                ldm_x4(af[mi], sA + (uint32_t)(wm + mi * 16 + arow) * ASTRIDE_B + kk * 2 + acol);
#pragma unroll
            for (int p = 0; p < 2; ++p) {
                uint32_t rh[4], rl[4];
                ldm_x4(rh, sBh + (uint32_t)(wn + p * 16 + brow) * ASTRIDE_B + kk * 2 + bcol);
                ldm_x4(rl, sBl + (uint32_t)(wn + p * 16 + brow) * ASTRIDE_B + kk * 2 + bcol);
                bfh[2 * p][0] = rh[0]; bfh[2 * p][1] = rh[1];
                bfh[2 * p + 1][0] = rh[2]; bfh[2 * p + 1][1] = rh[3];
                bfl[2 * p][0] = rl[0]; bfl[2 * p][1] = rl[1];
                bfl[2 * p + 1][0] = rl[2]; bfl[2 * p + 1][1] = rl[3];
            }
#pragma unroll
            for (int mi = 0; mi < 4; ++mi)
#pragma unroll
                for (int ni = 0; ni < 4; ++ni) {
                    mma_f16(acc[mi][ni], af[mi], bfh[ni]);
                    mma_f16(acc[mi][ni], af[mi], bfl[ni]);
                }
        }
        __syncthreads();
    }

    const int lr = l >> 2;
#pragma unroll
    for (int mi = 0; mi < 4; ++mi) {
        const int mrow = m0 + wm + mi * 16 + lr;
        const int b = mrow >> 11;
        const int s = mrow & (S_LEN - 1);
#pragma unroll
        for (int ni = 0; ni < 4; ++ni) {
            const int col = n0 + wn + ni * 8 + (l & 3) * 2;
            const float2 b2 = *(const float2*)&bias[col];
            float2 v0 = { acc[mi][ni][0] + b2.x, acc[mi][ni][1] + b2.y };
            float2 v1 = { acc[mi][ni][2] + b2.x, acc[mi][ni][3] + b2.y };
            if (EPI == 0) {
                *(float2*)&out[(size_t)mrow * DM + col] = v0;
                *(float2*)&out[(size_t)(mrow + 8) * DM + col] = v1;
            } else if (EPI == 1) {
                const int hd = col >> 6, d = col & 63;
                const size_t base = ((size_t)(b * NH + hd) * S_LEN + s) * DK + d;
                *(uint32_t*)&oh[base] = packh(v0.x, v0.y);
                *(uint32_t*)&oh[base + 8 * DK] = packh(v1.x, v1.y);
            } else if (EPI == 2) {
                const int hd = col >> 6, d = col & 63;
                const size_t base = ((size_t)(b * NH + hd) * S_LEN + s) * DK + d;
                float hx = __half2float(__float2half_rn(v0.x));
                float hy = __half2float(__float2half_rn(v0.y));
                *(uint32_t*)&oh[base] = packh(v0.x, v0.y);
                *(uint32_t*)&ol[base] = packh(v0.x - hx, v0.y - hy);
                hx = __half2float(__float2half_rn(v1.x));
                hy = __half2float(__float2half_rn(v1.y));
                *(uint32_t*)&oh[base + 8 * DK] = packh(v1.x, v1.y);
                *(uint32_t*)&ol[base + 8 * DK] = packh(v1.x - hx, v1.y - hy);
            } else {
                const int hd = col >> 6, d = col & 63;
                const size_t rb = ((size_t)(b * NH + hd) * DK + d) * S_LEN;
                float h;
                h = __half2float(__float2half_rn(v0.x));
                oh[rb + s] = __float2half_rn(v0.x);
                ol[rb + s] = __float2half_rn(v0.x - h);
                h = __half2float(__float2half_rn(v0.y));
                oh[rb + S_LEN + s] = __float2half_rn(v0.y);
                ol[rb + S_LEN + s] = __float2half_rn(v0.y - h);
                h = __half2float(__float2half_rn(v1.x));
                oh[rb + s + 8] = __float2half_rn(v1.x);
                ol[rb + s + 8] = __float2half_rn(v1.x - h);
                h = __half2float(__float2half_rn(v1.y));
                oh[rb + S_LEN + s + 8] = __float2half_rn(v1.y);
                ol[rb + S_LEN + s + 8] = __float2half_rn(v1.y - h);
            }
        }
    }
}

// ---------------- fp16x2 mma.sync flash attention (ldmatrix) ----------------
#define RSTR      144
#define AOFF_Q    0
#define AOFF_KH   18432
#define AOFF_KL   36864
#define AOFF_VH   55296
#define AOFF_VL   73728
#define AOFF_MSK  92160
#define ASMEM     100352

__global__ void __launch_bounds__(256, 1) attn_mma(const __half* __restrict__ Q,
                                                   const __half* __restrict__ Kh,
                                                   const __half* __restrict__ Kl,
                                                   const __half* __restrict__ Vh,
                                                   const __half* __restrict__ Vl,
                                                   const int* __restrict__ mask,
                                                   __half* __restrict__ om)
{
    extern __shared__ char smem[];
    const uint32_t smb = smem_u32(smem);
    const int tid = threadIdx.x;
    const int w   = tid >> 5;
    const int l   = tid & 31;
    const int bh  = blockIdx.y;
    const int bb  = bh >> 4;
    const int hh  = bh & 15;
    const int q0  = blockIdx.x * 128;
    const int wq0 = w * 16;
    const int r   = l >> 2;
    const int cg  = l & 3;

    const int g    = l >> 3;
    const int arow = (g & 1) * 8 + (l & 7);
    const int acol = (g >> 1) * 16;
    const int brow = (g >> 1) * 8 + (l & 7);
    const int bcol = (g & 1) * 16;

#pragma unroll
    for (int p = 0; p < 4; ++p) {
        const int idx = tid + p * 256;
        const int row = idx >> 3, ci = idx & 7;
        cp16(smb + AOFF_Q + row * RSTR + ci * 16,
             Q + ((size_t)bh * S_LEN + q0 + row) * DK + ci * 8);
    }

    auto load_kv = [&](int kt, int buf) {
#pragma unroll
        for (int p = 0; p < 2; ++p) {
            const int idx = tid + p * 256;
            const int row = idx >> 3, ci = idx & 7;
            const uint32_t dst = (uint32_t)row * RSTR + ci * 16 + buf * 9216;
            cp16(smb + AOFF_KH + dst, Kh + ((size_t)bh * S_LEN + kt + row) * DK + ci * 8);
            cp16(smb + AOFF_KL + dst, Kl + ((size_t)bh * S_LEN + kt + row) * DK + ci * 8);
            cp16(smb + AOFF_VH + dst, Vh + ((size_t)bh * DK + row) * S_LEN + kt + ci * 8);
            cp16(smb + AOFF_VL + dst, Vl + ((size_t)bh * DK + row) * S_LEN + kt + ci * 8);
        }
        CP_COMMIT();
    };
    load_kv(0, 0);

    int* msks = (int*)(smem + AOFF_MSK);
#pragma unroll
    for (int p = 0; p < 2; ++p) {
        const int i = tid + p * 256;
        *(int4*)&msks[i * 4] = *(const int4*)&mask[(size_t)bb * S_LEN + i * 4];
    }

    uint32_t qf[4][4];
    float o[8][4];
#pragma unroll
    for (int nj = 0; nj < 8; ++nj)
#pragma unroll
        for (int j = 0; j < 4; ++j) o[nj][j] = 0.f;
    float m0 = -INFINITY, m1 = -INFINITY, l0 = 0.f, l1 = 0.f;

    const int NIT = S_LEN / 64;
    for (int it = 0; it < NIT; ++it) {
        const int kt = it * 64;
        const int buf = it & 1;
        if (it + 1 < NIT) {
            load_kv(kt + 64, buf ^ 1);
            CP_WAIT(1);
        } else {
            CP_WAIT(0);
        }
        __syncthreads();

        if (it == 0) {
#pragma unroll
            for (int k = 0; k < 4; ++k)
                ldm_x4(qf[k], smb + AOFF_Q + (uint32_t)(wq0 + arow) * RSTR + k * 32 + acol);
        }

        // ---- S = Q K^T ----
        float s[8][4];
#pragma unroll
        for (int nj = 0; nj < 8; ++nj)
#pragma unroll
            for (int j = 0; j < 4; ++j) s[nj][j] = 0.f;

#pragma unroll
        for (int k = 0; k < 4; ++k)
#pragma unroll
            for (int p = 0; p < 4; ++p) {
                const uint32_t kb = (uint32_t)(p * 16 + brow) * RSTR + k * 32 + bcol + buf * 9216;
                uint32_t rh[4], rl[4];
                ldm_x4(rh, smb + AOFF_KH + kb);
                ldm_x4(rl, smb + AOFF_KL + kb);
                mma_f16(s[2 * p],     qf[k], rh);
                mma_f16(s[2 * p],     qf[k], rl);
                mma_f16(s[2 * p + 1], qf[k], rh + 2);
                mma_f16(s[2 * p + 1], qf[k], rl + 2);
            }

        // ---- mask + scale + online softmax ----
        float mx0 = -INFINITY, mx1 = -INFINITY;
#pragma unroll
        for (int nj = 0; nj < 8; ++nj) {
            const int kc = kt + nj * 8 + cg * 2;
            const bool a0 = msks[kc] != 0;
            const bool a1 = msks[kc + 1] != 0;
            s[nj][0] = a0 ? s[nj][0] * 0.125f : -1e9f;
            s[nj][1] = a1 ? s[nj][1] * 0.125f : -1e9f;
            s[nj][2] = a0 ? s[nj][2] * 0.125f : -1e9f;
            s[nj][3] = a1 ? s[nj][3] * 0.125f : -1e9f;
            mx0 = fmaxf(mx0, fmaxf(s[nj][0], s[nj][1]));
            mx1 = fmaxf(mx1, fmaxf(s[nj][2], s[nj][3]));
        }
        mx0 = fmaxf(mx0, __shfl_xor_sync(0xffffffffu, mx0, 1));
        mx0 = fmaxf(mx0, __shfl_xor_sync(0xffffffffu, mx0, 2));
        mx1 = fmaxf(mx1, __shfl_xor_sync(0xffffffffu, mx1, 1));
        mx1 = fmaxf(mx1, __shfl_xor_sync(0xffffffffu, mx1, 2));

        const float nm0 = fmaxf(m0, mx0);
        const float nm1 = fmaxf(m1, mx1);
        const float f0 = __expf(m0 - nm0);
        const float f1 = __expf(m1 - nm1);
        m0 = nm0; m1 = nm1;

        uint32_t ph[4][4];
        float la0 = 0.f, la1 = 0.f;
#pragma unroll
        for (int nj = 0; nj < 8; ++nj) {
            const float p0 = __expf(s[nj][0] - m0);
            const float p1 = __expf(s[nj][1] - m0);
            const float p2 = __expf(s[nj][2] - m1);
            const float p3 = __expf(s[nj][3] - m1);
            la0 += p0 + p1;
            la1 += p2 + p3;
            const int t = nj >> 1;
            if ((nj & 1) == 0) {
                ph[t][0] = packh(p0, p1);
                ph[t][1] = packh(p2, p3);
            } else {
                ph[t][2] = packh(p0, p1);
                ph[t][3] = packh(p2, p3);
            }
        }
        la0 += __shfl_xor_sync(0xffffffffu, la0, 1);
        la0 += __shfl_xor_sync(0xffffffffu, la0, 2);
        la1 += __shfl_xor_sync(0xffffffffu, la1, 1);
        la1 += __shfl_xor_sync(0xffffffffu, la1, 2);
        l0 = l0 * f0 + la0;
        l1 = l1 * f1 + la1;

#pragma unroll
        for (int nj = 0; nj < 8; ++nj) {
            o[nj][0] *= f0; o[nj][1] *= f0;
            o[nj][2] *= f1; o[nj][3] *= f1;
        }

        // ---- O += P V ----
#pragma unroll
        for (int t = 0; t < 4; ++t)
#pragma unroll
            for (int p = 0; p < 4; ++p) {
                const uint32_t vb = (uint32_t)(p * 16 + brow) * RSTR + t * 32 + bcol + buf * 9216;
                uint32_t rh[4], rl[4];
                ldm_x4(rh, smb + AOFF_VH + vb);
                ldm_x4(rl, smb + AOFF_VL + vb);
                mma_f16(o[2 * p],     ph[t], rh);
                mma_f16(o[2 * p],     ph[t], rl);
                mma_f16(o[2 * p + 1], ph[t], rh + 2);
                mma_f16(o[2 * p + 1], ph[t], rl + 2);
            }
        __syncthreads();
    }

    // ---- epilogue ----
    const float inv0 = 1.f / l0;
    const float inv1 = 1.f / l1;
    const int s0r = q0 + wq0 + r;
    const int s1r = s0r + 8;
#pragma unroll
    for (int nj = 0; nj < 8; ++nj) {
        const int col = hh * 64 + nj * 8 + cg * 2;
        float x0 = o[nj][0] * inv0, y0 = o[nj][1] * inv0;
        float x1 = o[nj][2] * inv1, y1 = o[nj][3] * inv1;
        *(uint32_t*)&om[((size_t)(bb * S_LEN + s0r)) * DM + col] = packh(x0, y0);
        *(uint32_t*)&om[((size_t)(bb * S_LEN + s1r)) * DM + col] = packh(x1, y1);
    }
}

// ---------------- launch ----------------
extern "C" void kernel_launch(void* const* d_in, const int* in_sizes, int n_in,
                              void* d_out, int out_size) {
    const float* q  = (const float*)d_in[0];
    const float* k  = (const float*)d_in[1];
    const float* v  = (const float*)d_in[2];
    const int*   mk = (const int*)  d_in[3];
    const float* wq = (const float*)d_in[4];
    const float* bq = (const float*)d_in[5];
    const float* wk = (const float*)d_in[6];
    const float* bk = (const float*)d_in[7];
    const float* wv = (const float*)d_in[8];
    const float* bv = (const float*)d_in[9];
    const float* wo = (const float*)d_in[10];
    const float* bo = (const float*)d_in[11];
    float* out = (float*)d_out;

    __half *xa, *wh, *wl, *qf, *kh, *kl, *vh, *vl, *om;
    cudaGetSymbolAddress((void**)&xa, g_xa);
    cudaGetSymbolAddress((void**)&wh, g_wh);
    cudaGetSymbolAddress((void**)&wl, g_wl);
    cudaGetSymbolAddress((void**)&qf, g_q);
    cudaGetSymbolAddress((void**)&kh, g_kh);
    cudaGetSymbolAddress((void**)&kl, g_kl);
    cudaGetSymbolAddress((void**)&vh, g_vh);
    cudaGetSymbolAddress((void**)&vl, g_vl);
    cudaGetSymbolAddress((void**)&om, g_om);

    cudaFuncSetAttribute(gemm_mma<0>, cudaFuncAttributeMaxDynamicSharedMemorySize, GSMEM);
    cudaFuncSetAttribute(gemm_mma<1>, cudaFuncAttributeMaxDynamicSharedMemorySize, GSMEM);
    cudaFuncSetAttribute(gemm_mma<2>, cudaFuncAttributeMaxDynamicSharedMemorySize, GSMEM);
    cudaFuncSetAttribute(gemm_mma<3>, cudaFuncAttributeMaxDynamicSharedMemorySize, GSMEM);
    cudaFuncSetAttribute(attn_mma, cudaFuncAttributeMaxDynamicSharedMemorySize, ASMEM);

    const int nx4 = MTOT * DM / 4;
    const int nw4 = DM * DM / 4;
    dim3 gg(DM / 128, MTOT / 128);

    trunc_x<<<(nx4 + 255) / 256, 256>>>(q, xa, nx4);
    split_w<<<(nw4 + 255) / 256, 256>>>(wq, wh, wl, nw4);
    gemm_mma<1><<<gg, 256, GSMEM>>>(xa, wh, wl, bq, nullptr, qf, nullptr);

    trunc_x<<<(nx4 + 255) / 256, 256>>>(k, xa, nx4);
    split_w<<<(nw4 + 255) / 256, 256>>>(wk, wh, wl, nw4);
    gemm_mma<2><<<gg, 256, GSMEM>>>(xa, wh, wl, bk, nullptr, kh, kl);

    trunc_x<<<(nx4 + 255) / 256, 256>>>(v, xa, nx4);
    split_w<<<(nw4 + 255) / 256, 256>>>(wv, wh, wl, nw4);
    gemm_mma<3><<<gg, 256, GSMEM>>>(xa, wh, wl, bv, nullptr, vh, vl);

    dim3 ga(S_LEN / 128, B_SZ * NH);
    attn_mma<<<ga, 256, ASMEM>>>(qf, kh, kl, vh, vl, mk, om);

    split_w<<<(nw4 + 255) / 256, 256>>>(wo, wh, wl, nw4);
    gemm_mma<0><<<gg, 256, GSMEM>>>(om, wh, wl, bo, out, nullptr, nullptr);
}

// round 7
// speedup vs baseline: 4.2646x; 1.2069x over previous
#include <cuda_runtime.h>
#include <cuda_fp16.h>
#include <math.h>
#include <cstdint>

#define B_SZ  4
#define S_LEN 2048
#define DM    1024
#define NH    16
#define DK    64
#define MTOT  (B_SZ * S_LEN)   // 8192

// ---------------- scratch (device globals) ----------------
__device__ __half g_xa[(size_t)MTOT * DM];
__device__ __half g_wh[(size_t)DM * DM];
__device__ __half g_wl[(size_t)DM * DM];
__device__ __half g_q[(size_t)B_SZ * NH * S_LEN * DK];
__device__ __half g_k[(size_t)B_SZ * NH * S_LEN * DK];
__device__ __half g_vt[(size_t)B_SZ * NH * DK * S_LEN];   // V^T
__device__ __half g_om[(size_t)MTOT * DM];

// ---------------- helpers ----------------
__device__ __forceinline__ uint32_t smem_u32(const void* p) {
    uint32_t a;
    asm("{ .reg .u64 t; cvta.to.shared.u64 t, %1; cvt.u32.u64 %0, t; }" : "=r"(a) : "l"(p));
    return a;
}
__device__ __forceinline__ void cp16(uint32_t dst, const void* src) {
    asm volatile("cp.async.cg.shared.global [%0], [%1], 16;" :: "r"(dst), "l"(src) : "memory");
}
#define CP_COMMIT() asm volatile("cp.async.commit_group;" ::: "memory")
#define CP_WAIT(n)  asm volatile("cp.async.wait_group %0;" :: "n"(n) : "memory")

__device__ __forceinline__ void mma_f16(float* d, const uint32_t* a, const uint32_t* b) {
    asm volatile(
        "mma.sync.aligned.m16n8k16.row.col.f32.f16.f16.f32 "
        "{%0,%1,%2,%3}, {%4,%5,%6,%7}, {%8,%9}, {%0,%1,%2,%3};"
        : "+f"(d[0]), "+f"(d[1]), "+f"(d[2]), "+f"(d[3])
        : "r"(a[0]), "r"(a[1]), "r"(a[2]), "r"(a[3]), "r"(b[0]), "r"(b[1]));
}
__device__ __forceinline__ void ldm_x4(uint32_t* r, uint32_t addr) {
    asm volatile("ldmatrix.sync.aligned.m8n8.x4.shared.b16 {%0,%1,%2,%3}, [%4];"
        : "=r"(r[0]), "=r"(r[1]), "=r"(r[2]), "=r"(r[3]) : "r"(addr));
}
__device__ __forceinline__ uint32_t packh(float a, float b) {
    __half2 t = __floats2half2_rn(a, b);
    return *(uint32_t*)&t;
}

// ---------------- fp32 -> fp16 truncation / hi-lo split ----------------
__global__ void __launch_bounds__(256) trunc_x(const float* __restrict__ x,
                                               __half* __restrict__ o, int n4)
{
    int i = blockIdx.x * 256 + threadIdx.x;
    if (i >= n4) return;
    float4 v = ((const float4*)x)[i];
    ((__half2*)o)[i * 2 + 0] = __floats2half2_rn(v.x, v.y);
    ((__half2*)o)[i * 2 + 1] = __floats2half2_rn(v.z, v.w);
}

__global__ void __launch_bounds__(256) split_w(const float* __restrict__ x,
                                               __half* __restrict__ hi,
                                               __half* __restrict__ lo, int n4)
{
    int i = blockIdx.x * 256 + threadIdx.x;
    if (i >= n4) return;
    float4 v = ((const float4*)x)[i];
    __half h0 = __float2half_rn(v.x);
    __half h1 = __float2half_rn(v.y);
    __half h2 = __float2half_rn(v.z);
    __half h3 = __float2half_rn(v.w);
    ((__half2*)hi)[i * 2 + 0] = __half2(h0, h1);
    ((__half2*)hi)[i * 2 + 1] = __half2(h2, h3);
    ((__half2*)lo)[i * 2 + 0] = __floats2half2_rn(v.x - __half2float(h0), v.y - __half2float(h1));
    ((__half2*)lo)[i * 2 + 1] = __floats2half2_rn(v.z - __half2float(h2), v.w - __half2float(h3));
}

// ---------------- fp16x2 mma.sync GEMM (ldmatrix fragments) ----------------
// EPI: 0 = fp32 row-major; 1 = head-split f16 [bh][s][d]; 2 = transposed f16 [bh][d][s]
#define BK        32
#define NCHUNK    (DM / BK)
#define ASTRIDE_B 80
#define TILE_B    (128 * ASTRIDE_B)
#define GSMEM     (2 * 3 * TILE_B)

template<int EPI>
__global__ void __launch_bounds__(256, 1) gemm_mma(const __half* __restrict__ A,
                                                   const __half* __restrict__ Bh,
                                                   const __half* __restrict__ Bl,
                                                   const float* __restrict__ bias,
                                                   float* __restrict__ out,
                                                   __half* __restrict__ oh)
{
    extern __shared__ char smem[];
    const uint32_t smb = smem_u32(smem);
    const int tid = threadIdx.x;
    const int w   = tid >> 5;
    const int l   = tid & 31;
    const int m0  = blockIdx.y * 128;
    const int n0  = blockIdx.x * 128;
    const int wm  = (w & 1) * 64;
    const int wn  = (w >> 1) * 32;

    const int i0 = tid, i1 = tid + 256;
    const int r0 = i0 >> 2, c0 = i0 & 3;
    const int r1 = i1 >> 2, c1 = i1 & 3;

    auto buf_off = [](int buf, int t) -> uint32_t {
        return (uint32_t)(buf * 3 + t) * TILE_B;
    };

    auto load_chunk = [&](int ck, int buf) {
        const size_t ko = (size_t)ck * BK;
        const uint32_t s0 = (uint32_t)r0 * ASTRIDE_B + c0 * 16;
        const uint32_t s1 = (uint32_t)r1 * ASTRIDE_B + c1 * 16;
        cp16(smb + buf_off(buf, 0) + s0, A  + (size_t)(m0 + r0) * DM + ko + c0 * 8);
        cp16(smb + buf_off(buf, 0) + s1, A  + (size_t)(m0 + r1) * DM + ko + c1 * 8);
        cp16(smb + buf_off(buf, 1) + s0, Bh + (size_t)(n0 + r0) * DM + ko + c0 * 8);
        cp16(smb + buf_off(buf, 1) + s1, Bh + (size_t)(n0 + r1) * DM + ko + c1 * 8);
        cp16(smb + buf_off(buf, 2) + s0, Bl + (size_t)(n0 + r0) * DM + ko + c0 * 8);
        cp16(smb + buf_off(buf, 2) + s1, Bl + (size_t)(n0 + r1) * DM + ko + c1 * 8);
        CP_COMMIT();
    };

    float acc[4][4][4];
#pragma unroll
    for (int mi = 0; mi < 4; ++mi)
#pragma unroll
        for (int ni = 0; ni < 4; ++ni)
#pragma unroll
            for (int j = 0; j < 4; ++j) acc[mi][ni][j] = 0.f;

    load_chunk(0, 0);

    const int g    = l >> 3;
    const int arow = (g & 1) * 8 + (l & 7);
    const int acol = (g >> 1) * 16;
    const int brow = (g >> 1) * 8 + (l & 7);
    const int bcol = (g & 1) * 16;

    for (int ck = 0; ck < NCHUNK; ++ck) {
        const int buf = ck & 1;
        if (ck + 1 < NCHUNK) {
            load_chunk(ck + 1, buf ^ 1);
            CP_WAIT(1);
        } else {
            CP_WAIT(0);
        }
        __syncthreads();

        const uint32_t sA  = smb + buf_off(buf, 0);
        const uint32_t sBh = smb + buf_off(buf, 1);
        const uint32_t sBl = smb + buf_off(buf, 2);

#pragma unroll
        for (int kk = 0; kk < BK; kk += 16) {
            uint32_t af[4][4], bfh[4][2], bfl[4][2];
#pragma unroll
            for (int mi = 0; mi < 4; ++mi)
                ldm_x4(af[mi], sA + (uint32_t)(wm + mi * 16 + arow) * ASTRIDE_B + kk * 2 + acol);
#pragma unroll
            for (int p = 0; p < 2; ++p) {
                uint32_t rh[4], rl[4];
                ldm_x4(rh, sBh + (uint32_t)(wn + p * 16 + brow) * ASTRIDE_B + kk * 2 + bcol);
                ldm_x4(rl, sBl + (uint32_t)(wn + p * 16 + brow) * ASTRIDE_B + kk * 2 + bcol);
                bfh[2 * p][0] = rh[0]; bfh[2 * p][1] = rh[1];
                bfh[2 * p + 1][0] = rh[2]; bfh[2 * p + 1][1] = rh[3];
                bfl[2 * p][0] = rl[0]; bfl[2 * p][1] = rl[1];
                bfl[2 * p + 1][0] = rl[2]; bfl[2 * p + 1][1] = rl[3];
            }
#pragma unroll
            for (int mi = 0; mi < 4; ++mi)
#pragma unroll
                for (int ni = 0; ni < 4; ++ni) {
                    mma_f16(acc[mi][ni], af[mi], bfh[ni]);
                    mma_f16(acc[mi][ni], af[mi], bfl[ni]);
                }
        }
        __syncthreads();
    }

    const int lr = l >> 2;
#pragma unroll
    for (int mi = 0; mi < 4; ++mi) {
        const int mrow = m0 + wm + mi * 16 + lr;
        const int b = mrow >> 11;
        const int s = mrow & (S_LEN - 1);
#pragma unroll
        for (int ni = 0; ni < 4; ++ni) {
            const int col = n0 + wn + ni * 8 + (l & 3) * 2;
            const float2 b2 = *(const float2*)&bias[col];
            float2 v0 = { acc[mi][ni][0] + b2.x, acc[mi][ni][1] + b2.y };
            float2 v1 = { acc[mi][ni][2] + b2.x, acc[mi][ni][3] + b2.y };
            if (EPI == 0) {
                *(float2*)&out[(size_t)mrow * DM + col] = v0;
                *(float2*)&out[(size_t)(mrow + 8) * DM + col] = v1;
            } else if (EPI == 1) {
                const int hd = col >> 6, d = col & 63;
                const size_t base = ((size_t)(b * NH + hd) * S_LEN + s) * DK + d;
                *(uint32_t*)&oh[base] = packh(v0.x, v0.y);
                *(uint32_t*)&oh[base + 8 * DK] = packh(v1.x, v1.y);
            } else {
                const int hd = col >> 6, d = col & 63;
                const size_t rb = ((size_t)(b * NH + hd) * DK + d) * S_LEN;
                oh[rb + s] = __float2half_rn(v0.x);
                oh[rb + S_LEN + s] = __float2half_rn(v0.y);
                oh[rb + s + 8] = __float2half_rn(v1.x);
                oh[rb + S_LEN + s + 8] = __float2half_rn(v1.y);
            }
        }
    }
}

// ---------------- fp16 mma.sync flash attention (single-product) ----------------
#define RSTR      144
#define AOFF_Q    0                 // 128*144 = 18432
#define AOFF_K    18432             // 2 bufs x 9216
#define AOFF_V    36864             // 2 bufs x 9216
#define AOFF_MSK  55296
#define ASMEM     63488

__global__ void __launch_bounds__(256, 1) attn_mma(const __half* __restrict__ Q,
                                                   const __half* __restrict__ K,
                                                   const __half* __restrict__ V,
                                                   const int* __restrict__ mask,
                                                   __half* __restrict__ om)
{
    extern __shared__ char smem[];
    const uint32_t smb = smem_u32(smem);
    const int tid = threadIdx.x;
    const int w   = tid >> 5;
    const int l   = tid & 31;
    const int bh  = blockIdx.y;
    const int bb  = bh >> 4;
    const int hh  = bh & 15;
    const int q0  = blockIdx.x * 128;
    const int wq0 = w * 16;
    const int r   = l >> 2;
    const int cg  = l & 3;

    const int g    = l >> 3;
    const int arow = (g & 1) * 8 + (l & 7);
    const int acol = (g >> 1) * 16;
    const int brow = (g >> 1) * 8 + (l & 7);
    const int bcol = (g & 1) * 16;

#pragma unroll
    for (int p = 0; p < 4; ++p) {
        const int idx = tid + p * 256;
        const int row = idx >> 3, ci = idx & 7;
        cp16(smb + AOFF_Q + row * RSTR + ci * 16,
             Q + ((size_t)bh * S_LEN + q0 + row) * DK + ci * 8);
    }

    auto load_kv = [&](int kt, int buf) {
#pragma unroll
        for (int p = 0; p < 2; ++p) {
            const int idx = tid + p * 256;
            const int row = idx >> 3, ci = idx & 7;
            const uint32_t dst = (uint32_t)row * RSTR + ci * 16 + buf * 9216;
            cp16(smb + AOFF_K + dst, K + ((size_t)bh * S_LEN + kt + row) * DK + ci * 8);
            cp16(smb + AOFF_V + dst, V + ((size_t)bh * DK + row) * S_LEN + kt + ci * 8);
        }
        CP_COMMIT();
    };
    load_kv(0, 0);

    int* msks = (int*)(smem + AOFF_MSK);
#pragma unroll
    for (int p = 0; p < 2; ++p) {
        const int i = tid + p * 256;
        *(int4*)&msks[i * 4] = *(const int4*)&mask[(size_t)bb * S_LEN + i * 4];
    }

    uint32_t qf[4][4];
    float o[8][4];
#pragma unroll
    for (int nj = 0; nj < 8; ++nj)
#pragma unroll
        for (int j = 0; j < 4; ++j) o[nj][j] = 0.f;
    float m0 = -INFINITY, m1 = -INFINITY, l0 = 0.f, l1 = 0.f;

    const int NIT = S_LEN / 64;
    for (int it = 0; it < NIT; ++it) {
        const int kt = it * 64;
        const int buf = it & 1;
        if (it + 1 < NIT) {
            load_kv(kt + 64, buf ^ 1);
            CP_WAIT(1);
        } else {
            CP_WAIT(0);
        }
        __syncthreads();

        if (it == 0) {
#pragma unroll
            for (int k = 0; k < 4; ++k)
                ldm_x4(qf[k], smb + AOFF_Q + (uint32_t)(wq0 + arow) * RSTR + k * 32 + acol);
        }

        // ---- S = Q K^T ----
        float s[8][4];
#pragma unroll
        for (int nj = 0; nj < 8; ++nj)
#pragma unroll
            for (int j = 0; j < 4; ++j) s[nj][j] = 0.f;

#pragma unroll
        for (int k = 0; k < 4; ++k)
#pragma unroll
            for (int p = 0; p < 4; ++p) {
                const uint32_t kb = (uint32_t)(p * 16 + brow) * RSTR + k * 32 + bcol + buf * 9216;
                uint32_t rh[4];
                ldm_x4(rh, smb + AOFF_K + kb);
                mma_f16(s[2 * p],     qf[k], rh);
                mma_f16(s[2 * p + 1], qf[k], rh + 2);
            }

        // ---- mask + scale + online softmax ----
        float mx0 = -INFINITY, mx1 = -INFINITY;
#pragma unroll
        for (int nj = 0; nj < 8; ++nj) {
            const int kc = kt + nj * 8 + cg * 2;
            const bool a0 = msks[kc] != 0;
            const bool a1 = msks[kc + 1] != 0;
            s[nj][0] = a0 ? s[nj][0] * 0.125f : -1e9f;
            s[nj][1] = a1 ? s[nj][1] * 0.125f : -1e9f;
            s[nj][2] = a0 ? s[nj][2] * 0.125f : -1e9f;
            s[nj][3] = a1 ? s[nj][3] * 0.125f : -1e9f;
            mx0 = fmaxf(mx0, fmaxf(s[nj][0], s[nj][1]));
            mx1 = fmaxf(mx1, fmaxf(s[nj][2], s[nj][3]));
        }
        mx0 = fmaxf(mx0, __shfl_xor_sync(0xffffffffu, mx0, 1));
        mx0 = fmaxf(mx0, __shfl_xor_sync(0xffffffffu, mx0, 2));
        mx1 = fmaxf(mx1, __shfl_xor_sync(0xffffffffu, mx1, 1));
        mx1 = fmaxf(mx1, __shfl_xor_sync(0xffffffffu, mx1, 2));

        const float nm0 = fmaxf(m0, mx0);
        const float nm1 = fmaxf(m1, mx1);
        const float f0 = __expf(m0 - nm0);
        const float f1 = __expf(m1 - nm1);
        m0 = nm0; m1 = nm1;

        uint32_t ph[4][4];
        float la0 = 0.f, la1 = 0.f;
#pragma unroll
        for (int nj = 0; nj < 8; ++nj) {
            const float p0 = __expf(s[nj][0] - m0);
            const float p1 = __expf(s[nj][1] - m0);
            const float p2 = __expf(s[nj][2] - m1);
            const float p3 = __expf(s[nj][3] - m1);
            la0 += p0 + p1;
            la1 += p2 + p3;
            const int t = nj >> 1;
            if ((nj & 1) == 0) {
                ph[t][0] = packh(p0, p1);
                ph[t][1] = packh(p2, p3);
            } else {
                ph[t][2] = packh(p0, p1);
                ph[t][3] = packh(p2, p3);
            }
        }
        la0 += __shfl_xor_sync(0xffffffffu, la0, 1);
        la0 += __shfl_xor_sync(0xffffffffu, la0, 2);
        la1 += __shfl_xor_sync(0xffffffffu, la1, 1);
        la1 += __shfl_xor_sync(0xffffffffu, la1, 2);
        l0 = l0 * f0 + la0;
        l1 = l1 * f1 + la1;

#pragma unroll
        for (int nj = 0; nj < 8; ++nj) {
            o[nj][0] *= f0; o[nj][1] *= f0;
            o[nj][2] *= f1; o[nj][3] *= f1;
        }

        // ---- O += P V ----
#pragma unroll
        for (int t = 0; t < 4; ++t)
#pragma unroll
            for (int p = 0; p < 4; ++p) {
                const uint32_t vb = (uint32_t)(p * 16 + brow) * RSTR + t * 32 + bcol + buf * 9216;
                uint32_t rh[4];
                ldm_x4(rh, smb + AOFF_V + vb);
                mma_f16(o[2 * p],     ph[t], rh);
                mma_f16(o[2 * p + 1], ph[t], rh + 2);
            }
        __syncthreads();
    }

    // ---- epilogue ----
    const float inv0 = 1.f / l0;
    const float inv1 = 1.f / l1;
    const int s0r = q0 + wq0 + r;
    const int s1r = s0r + 8;
#pragma unroll
    for (int nj = 0; nj < 8; ++nj) {
        const int col = hh * 64 + nj * 8 + cg * 2;
        float x0 = o[nj][0] * inv0, y0 = o[nj][1] * inv0;
        float x1 = o[nj][2] * inv1, y1 = o[nj][3] * inv1;
        *(uint32_t*)&om[((size_t)(bb * S_LEN + s0r)) * DM + col] = packh(x0, y0);
        *(uint32_t*)&om[((size_t)(bb * S_LEN + s1r)) * DM + col] = packh(x1, y1);
    }
}

// ---------------- launch ----------------
extern "C" void kernel_launch(void* const* d_in, const int* in_sizes, int n_in,
                              void* d_out, int out_size) {
    const float* q  = (const float*)d_in[0];
    const float* k  = (const float*)d_in[1];
    const float* v  = (const float*)d_in[2];
    const int*   mk = (const int*)  d_in[3];
    const float* wq = (const float*)d_in[4];
    const float* bq = (const float*)d_in[5];
    const float* wk = (const float*)d_in[6];
    const float* bk = (const float*)d_in[7];
    const float* wv = (const float*)d_in[8];
    const float* bv = (const float*)d_in[9];
    const float* wo = (const float*)d_in[10];
    const float* bo = (const float*)d_in[11];
    float* out = (float*)d_out;

    __half *xa, *wh, *wl, *qf, *kf, *vt, *om;
    cudaGetSymbolAddress((void**)&xa, g_xa);
    cudaGetSymbolAddress((void**)&wh, g_wh);
    cudaGetSymbolAddress((void**)&wl, g_wl);
    cudaGetSymbolAddress((void**)&qf, g_q);
    cudaGetSymbolAddress((void**)&kf, g_k);
    cudaGetSymbolAddress((void**)&vt, g_vt);
    cudaGetSymbolAddress((void**)&om, g_om);

    cudaFuncSetAttribute(gemm_mma<0>, cudaFuncAttributeMaxDynamicSharedMemorySize, GSMEM);
    cudaFuncSetAttribute(gemm_mma<1>, cudaFuncAttributeMaxDynamicSharedMemorySize, GSMEM);
    cudaFuncSetAttribute(gemm_mma<2>, cudaFuncAttributeMaxDynamicSharedMemorySize, GSMEM);
    cudaFuncSetAttribute(attn_mma, cudaFuncAttributeMaxDynamicSharedMemorySize, ASMEM);

    const int nx4 = MTOT * DM / 4;
    const int nw4 = DM * DM / 4;
    dim3 gg(DM / 128, MTOT / 128);

    trunc_x<<<(nx4 + 255) / 256, 256>>>(q, xa, nx4);
    split_w<<<(nw4 + 255) / 256, 256>>>(wq, wh, wl, nw4);
    gemm_mma<1><<<gg, 256, GSMEM>>>(xa, wh, wl, bq, nullptr, qf);

    trunc_x<<<(nx4 + 255) / 256, 256>>>(k, xa, nx4);
    split_w<<<(nw4 + 255) / 256, 256>>>(wk, wh, wl, nw4);
    gemm_mma<1><<<gg, 256, GSMEM>>>(xa, wh, wl, bk, nullptr, kf);

    trunc_x<<<(nx4 + 255) / 256, 256>>>(v, xa, nx4);
    split_w<<<(nw4 + 255) / 256, 256>>>(wv, wh, wl, nw4);
    gemm_mma<2><<<gg, 256, GSMEM>>>(xa, wh, wl, bv, nullptr, vt);

    dim3 ga(S_LEN / 128, B_SZ * NH);
    attn_mma<<<ga, 256, ASMEM>>>(qf, kf, vt, mk, om);

    split_w<<<(nw4 + 255) / 256, 256>>>(wo, wh, wl, nw4);
    gemm_mma<0><<<gg, 256, GSMEM>>>(om, wh, wl, bo, out, nullptr);
}

// round 8
// speedup vs baseline: 5.4312x; 1.2735x over previous
#include <cuda_runtime.h>
#include <cuda_fp16.h>
#include <math.h>
#include <cstdint>

#define B_SZ  4
#define S_LEN 2048
#define DM    1024
#define NH    16
#define DK    64
#define MTOT  (B_SZ * S_LEN)   // 8192

// ---------------- scratch (device globals) ----------------
__device__ __half g_xa[(size_t)MTOT * DM];
__device__ __half g_w[(size_t)DM * DM];
__device__ __half g_q[(size_t)B_SZ * NH * S_LEN * DK];
__device__ __half g_k[(size_t)B_SZ * NH * S_LEN * DK];
__device__ __half g_vt[(size_t)B_SZ * NH * DK * S_LEN];   // V^T
__device__ __half g_om[(size_t)MTOT * DM];

// ---------------- helpers ----------------
__device__ __forceinline__ uint32_t smem_u32(const void* p) {
    uint32_t a;
    asm("{ .reg .u64 t; cvta.to.shared.u64 t, %1; cvt.u32.u64 %0, t; }" : "=r"(a) : "l"(p));
    return a;
}
__device__ __forceinline__ void cp16(uint32_t dst, const void* src) {
    asm volatile("cp.async.cg.shared.global [%0], [%1], 16;" :: "r"(dst), "l"(src) : "memory");
}
#define CP_COMMIT() asm volatile("cp.async.commit_group;" ::: "memory")
#define CP_WAIT(n)  asm volatile("cp.async.wait_group %0;" :: "n"(n) : "memory")

__device__ __forceinline__ void mma_f16(float* d, const uint32_t* a, const uint32_t* b) {
    asm volatile(
        "mma.sync.aligned.m16n8k16.row.col.f32.f16.f16.f32 "
        "{%0,%1,%2,%3}, {%4,%5,%6,%7}, {%8,%9}, {%0,%1,%2,%3};"
        : "+f"(d[0]), "+f"(d[1]), "+f"(d[2]), "+f"(d[3])
        : "r"(a[0]), "r"(a[1]), "r"(a[2]), "r"(a[3]), "r"(b[0]), "r"(b[1]));
}
__device__ __forceinline__ void ldm_x4(uint32_t* r, uint32_t addr) {
    asm volatile("ldmatrix.sync.aligned.m8n8.x4.shared.b16 {%0,%1,%2,%3}, [%4];"
        : "=r"(r[0]), "=r"(r[1]), "=r"(r[2]), "=r"(r[3]) : "r"(addr));
}
__device__ __forceinline__ uint32_t packh(float a, float b) {
    __half2 t = __floats2half2_rn(a, b);
    return *(uint32_t*)&t;
}

// ---------------- fp32 -> fp16 truncation ----------------
__global__ void __launch_bounds__(256) trunc_x(const float* __restrict__ x,
                                               __half* __restrict__ o, int n4)
{
    int i = blockIdx.x * 256 + threadIdx.x;
    if (i >= n4) return;
    float4 v = ((const float4*)x)[i];
    ((__half2*)o)[i * 2 + 0] = __floats2half2_rn(v.x, v.y);
    ((__half2*)o)[i * 2 + 1] = __floats2half2_rn(v.z, v.w);
}

// ---------------- fp16 mma.sync GEMM (single product, ldmatrix) ----------------
// EPI: 0 = fp32 row-major; 1 = head-split f16 [bh][s][d]; 2 = transposed f16 [bh][d][s]
#define BK        32
#define NCHUNK    (DM / BK)
#define ASTRIDE_B 80
#define TILE_B    (128 * ASTRIDE_B)
#define GSMEM     (2 * 2 * TILE_B)      // 40960

template<int EPI>
__global__ void __launch_bounds__(256, 1) gemm_mma(const __half* __restrict__ A,
                                                   const __half* __restrict__ B,
                                                   const float* __restrict__ bias,
                                                   float* __restrict__ out,
                                                   __half* __restrict__ oh)
{
    extern __shared__ char smem[];
    const uint32_t smb = smem_u32(smem);
    const int tid = threadIdx.x;
    const int w   = tid >> 5;
    const int l   = tid & 31;
    const int m0  = blockIdx.y * 128;
    const int n0  = blockIdx.x * 128;
    const int wm  = (w & 1) * 64;
    const int wn  = (w >> 1) * 32;

    const int i0 = tid, i1 = tid + 256;
    const int r0 = i0 >> 2, c0 = i0 & 3;
    const int r1 = i1 >> 2, c1 = i1 & 3;

    auto buf_off = [](int buf, int t) -> uint32_t {
        return (uint32_t)(buf * 2 + t) * TILE_B;
    };

    auto load_chunk = [&](int ck, int buf) {
        const size_t ko = (size_t)ck * BK;
        const uint32_t s0 = (uint32_t)r0 * ASTRIDE_B + c0 * 16;
        const uint32_t s1 = (uint32_t)r1 * ASTRIDE_B + c1 * 16;
        cp16(smb + buf_off(buf, 0) + s0, A + (size_t)(m0 + r0) * DM + ko + c0 * 8);
        cp16(smb + buf_off(buf, 0) + s1, A + (size_t)(m0 + r1) * DM + ko + c1 * 8);
        cp16(smb + buf_off(buf, 1) + s0, B + (size_t)(n0 + r0) * DM + ko + c0 * 8);
        cp16(smb + buf_off(buf, 1) + s1, B + (size_t)(n0 + r1) * DM + ko + c1 * 8);
        CP_COMMIT();
    };

    float acc[4][4][4];
#pragma unroll
    for (int mi = 0; mi < 4; ++mi)
#pragma unroll
        for (int ni = 0; ni < 4; ++ni)
#pragma unroll
            for (int j = 0; j < 4; ++j) acc[mi][ni][j] = 0.f;

    load_chunk(0, 0);

    const int g    = l >> 3;
    const int arow = (g & 1) * 8 + (l & 7);
    const int acol = (g >> 1) * 16;
    const int brow = (g >> 1) * 8 + (l & 7);
    const int bcol = (g & 1) * 16;

    for (int ck = 0; ck < NCHUNK; ++ck) {
        const int buf = ck & 1;
        if (ck + 1 < NCHUNK) {
            load_chunk(ck + 1, buf ^ 1);
            CP_WAIT(1);
        } else {
            CP_WAIT(0);
        }
        __syncthreads();

        const uint32_t sA = smb + buf_off(buf, 0);
        const uint32_t sB = smb + buf_off(buf, 1);

#pragma unroll
        for (int kk = 0; kk < BK; kk += 16) {
            uint32_t af[4][4], bf[4][2];
#pragma unroll
            for (int mi = 0; mi < 4; ++mi)
                ldm_x4(af[mi], sA + (uint32_t)(wm + mi * 16 + arow) * ASTRIDE_B + kk * 2 + acol);
#pragma unroll
            for (int p = 0; p < 2; ++p) {
                uint32_t rh[4];
                ldm_x4(rh, sB + (uint32_t)(wn + p * 16 + brow) * ASTRIDE_B + kk * 2 + bcol);
                bf[2 * p][0] = rh[0]; bf[2 * p][1] = rh[1];
                bf[2 * p + 1][0] = rh[2]; bf[2 * p + 1][1] = rh[3];
            }
#pragma unroll
            for (int mi = 0; mi < 4; ++mi)
#pragma unroll
                for (int ni = 0; ni < 4; ++ni)
                    mma_f16(acc[mi][ni], af[mi], bf[ni]);
        }
        __syncthreads();
    }

    const int lr = l >> 2;
#pragma unroll
    for (int mi = 0; mi < 4; ++mi) {
        const int mrow = m0 + wm + mi * 16 + lr;
        const int b = mrow >> 11;
        const int s = mrow & (S_LEN - 1);
#pragma unroll
        for (int ni = 0; ni < 4; ++ni) {
            const int col = n0 + wn + ni * 8 + (l & 3) * 2;
            const float2 b2 = *(const float2*)&bias[col];
            float2 v0 = { acc[mi][ni][0] + b2.x, acc[mi][ni][1] + b2.y };
            float2 v1 = { acc[mi][ni][2] + b2.x, acc[mi][ni][3] + b2.y };
            if (EPI == 0) {
                *(float2*)&out[(size_t)mrow * DM + col] = v0;
                *(float2*)&out[(size_t)(mrow + 8) * DM + col] = v1;
            } else if (EPI == 1) {
                const int hd = col >> 6, d = col & 63;
                const size_t base = ((size_t)(b * NH + hd) * S_LEN + s) * DK + d;
                *(uint32_t*)&oh[base] = packh(v0.x, v0.y);
                *(uint32_t*)&oh[base + 8 * DK] = packh(v1.x, v1.y);
            } else {
                const int hd = col >> 6, d = col & 63;
                const size_t rb = ((size_t)(b * NH + hd) * DK + d) * S_LEN;
                oh[rb + s] = __float2half_rn(v0.x);
                oh[rb + S_LEN + s] = __float2half_rn(v0.y);
                oh[rb + s + 8] = __float2half_rn(v1.x);
                oh[rb + S_LEN + s + 8] = __float2half_rn(v1.y);
            }
        }
    }
}

// ---------------- fp16 mma.sync flash attention (single-product) ----------------
#define RSTR      144
#define AOFF_Q    0                 // 128*144 = 18432
#define AOFF_K    18432             // 2 bufs x 9216
#define AOFF_V    36864             // 2 bufs x 9216
#define AOFF_MSK  55296
#define ASMEM     63488

__global__ void __launch_bounds__(256, 1) attn_mma(const __half* __restrict__ Q,
                                                   const __half* __restrict__ K,
                                                   const __half* __restrict__ V,
                                                   const int* __restrict__ mask,
                                                   __half* __restrict__ om)
{
    extern __shared__ char smem[];
    const uint32_t smb = smem_u32(smem);
    const int tid = threadIdx.x;
    const int w   = tid >> 5;
    const int l   = tid & 31;
    const int bh  = blockIdx.y;
    const int bb  = bh >> 4;
    const int hh  = bh & 15;
    const int q0  = blockIdx.x * 128;
    const int wq0 = w * 16;
    const int r   = l >> 2;
    const int cg  = l & 3;

    const int g    = l >> 3;
    const int arow = (g & 1) * 8 + (l & 7);
    const int acol = (g >> 1) * 16;
    const int brow = (g >> 1) * 8 + (l & 7);
    const int bcol = (g & 1) * 16;

#pragma unroll
    for (int p = 0; p < 4; ++p) {
        const int idx = tid + p * 256;
        const int row = idx >> 3, ci = idx & 7;
        cp16(smb + AOFF_Q + row * RSTR + ci * 16,
             Q + ((size_t)bh * S_LEN + q0 + row) * DK + ci * 8);
    }

    auto load_kv = [&](int kt, int buf) {
#pragma unroll
        for (int p = 0; p < 2; ++p) {
            const int idx = tid + p * 256;
            const int row = idx >> 3, ci = idx & 7;
            const uint32_t dst = (uint32_t)row * RSTR + ci * 16 + buf * 9216;
            cp16(smb + AOFF_K + dst, K + ((size_t)bh * S_LEN + kt + row) * DK + ci * 8);
            cp16(smb + AOFF_V + dst, V + ((size_t)bh * DK + row) * S_LEN + kt + ci * 8);
        }
        CP_COMMIT();
    };
    load_kv(0, 0);

    int* msks = (int*)(smem + AOFF_MSK);
#pragma unroll
    for (int p = 0; p < 2; ++p) {
        const int i = tid + p * 256;
        *(int4*)&msks[i * 4] = *(const int4*)&mask[(size_t)bb * S_LEN + i * 4];
    }

    uint32_t qf[4][4];
    float o[8][4];
#pragma unroll
    for (int nj = 0; nj < 8; ++nj)
#pragma unroll
        for (int j = 0; j < 4; ++j) o[nj][j] = 0.f;
    float m0 = -INFINITY, m1 = -INFINITY, l0 = 0.f, l1 = 0.f;

    const int NIT = S_LEN / 64;
    for (int it = 0; it < NIT; ++it) {
        const int kt = it * 64;
        const int buf = it & 1;
        if (it + 1 < NIT) {
            load_kv(kt + 64, buf ^ 1);
            CP_WAIT(1);
        } else {
            CP_WAIT(0);
        }
        __syncthreads();

        if (it == 0) {
#pragma unroll
            for (int k = 0; k < 4; ++k)
                ldm_x4(qf[k], smb + AOFF_Q + (uint32_t)(wq0 + arow) * RSTR + k * 32 + acol);
        }

        // ---- S = Q K^T ----
        float s[8][4];
#pragma unroll
        for (int nj = 0; nj < 8; ++nj)
#pragma unroll
            for (int j = 0; j < 4; ++j) s[nj][j] = 0.f;

#pragma unroll
        for (int k = 0; k < 4; ++k)
#pragma unroll
            for (int p = 0; p < 4; ++p) {
                const uint32_t kb = (uint32_t)(p * 16 + brow) * RSTR + k * 32 + bcol + buf * 9216;
                uint32_t rh[4];
                ldm_x4(rh, smb + AOFF_K + kb);
                mma_f16(s[2 * p],     qf[k], rh);
                mma_f16(s[2 * p + 1], qf[k], rh + 2);
            }

        // ---- mask + scale + online softmax ----
        float mx0 = -INFINITY, mx1 = -INFINITY;
#pragma unroll
        for (int nj = 0; nj < 8; ++nj) {
            const int kc = kt + nj * 8 + cg * 2;
            const bool a0 = msks[kc] != 0;
            const bool a1 = msks[kc + 1] != 0;
            s[nj][0] = a0 ? s[nj][0] * 0.125f : -1e9f;
            s[nj][1] = a1 ? s[nj][1] * 0.125f : -1e9f;
            s[nj][2] = a0 ? s[nj][2] * 0.125f : -1e9f;
            s[nj][3] = a1 ? s[nj][3] * 0.125f : -1e9f;
            mx0 = fmaxf(mx0, fmaxf(s[nj][0], s[nj][1]));
            mx1 = fmaxf(mx1, fmaxf(s[nj][2], s[nj][3]));
        }
        mx0 = fmaxf(mx0, __shfl_xor_sync(0xffffffffu, mx0, 1));
        mx0 = fmaxf(mx0, __shfl_xor_sync(0xffffffffu, mx0, 2));
        mx1 = fmaxf(mx1, __shfl_xor_sync(0xffffffffu, mx1, 1));
        mx1 = fmaxf(mx1, __shfl_xor_sync(0xffffffffu, mx1, 2));

        const float nm0 = fmaxf(m0, mx0);
        const float nm1 = fmaxf(m1, mx1);
        const float f0 = __expf(m0 - nm0);
        const float f1 = __expf(m1 - nm1);
        m0 = nm0; m1 = nm1;

        uint32_t ph[4][4];
        float la0 = 0.f, la1 = 0.f;
#pragma unroll
        for (int nj = 0; nj < 8; ++nj) {
            const float p0 = __expf(s[nj][0] - m0);
            const float p1 = __expf(s[nj][1] - m0);
            const float p2 = __expf(s[nj][2] - m1);
            const float p3 = __expf(s[nj][3] - m1);
            la0 += p0 + p1;
            la1 += p2 + p3;
            const int t = nj >> 1;
            if ((nj & 1) == 0) {
                ph[t][0] = packh(p0, p1);
                ph[t][1] = packh(p2, p3);
            } else {
                ph[t][2] = packh(p0, p1);
                ph[t][3] = packh(p2, p3);
            }
        }
        la0 += __shfl_xor_sync(0xffffffffu, la0, 1);
        la0 += __shfl_xor_sync(0xffffffffu, la0, 2);
        la1 += __shfl_xor_sync(0xffffffffu, la1, 1);
        la1 += __shfl_xor_sync(0xffffffffu, la1, 2);
        l0 = l0 * f0 + la0;
        l1 = l1 * f1 + la1;

#pragma unroll
        for (int nj = 0; nj < 8; ++nj) {
            o[nj][0] *= f0; o[nj][1] *= f0;
            o[nj][2] *= f1; o[nj][3] *= f1;
        }

        // ---- O += P V ----
#pragma unroll
        for (int t = 0; t < 4; ++t)
#pragma unroll
            for (int p = 0; p < 4; ++p) {
                const uint32_t vb = (uint32_t)(p * 16 + brow) * RSTR + t * 32 + bcol + buf * 9216;
                uint32_t rh[4];
                ldm_x4(rh, smb + AOFF_V + vb);
                mma_f16(o[2 * p],     ph[t], rh);
                mma_f16(o[2 * p + 1], ph[t], rh + 2);
            }
        __syncthreads();
    }

    // ---- epilogue ----
    const float inv0 = 1.f / l0;
    const float inv1 = 1.f / l1;
    const int s0r = q0 + wq0 + r;
    const int s1r = s0r + 8;
#pragma unroll
    for (int nj = 0; nj < 8; ++nj) {
        const int col = hh * 64 + nj * 8 + cg * 2;
        float x0 = o[nj][0] * inv0, y0 = o[nj][1] * inv0;
        float x1 = o[nj][2] * inv1, y1 = o[nj][3] * inv1;
        *(uint32_t*)&om[((size_t)(bb * S_LEN + s0r)) * DM + col] = packh(x0, y0);
        *(uint32_t*)&om[((size_t)(bb * S_LEN + s1r)) * DM + col] = packh(x1, y1);
    }
}

// ---------------- launch ----------------
extern "C" void kernel_launch(void* const* d_in, const int* in_sizes, int n_in,
                              void* d_out, int out_size) {
    const float* q  = (const float*)d_in[0];
    const float* k  = (const float*)d_in[1];
    const float* v  = (const float*)d_in[2];
    const int*   mk = (const int*)  d_in[3];
    const float* wq = (const float*)d_in[4];
    const float* bq = (const float*)d_in[5];
    const float* wk = (const float*)d_in[6];
    const float* bk = (const float*)d_in[7];
    const float* wv = (const float*)d_in[8];
    const float* bv = (const float*)d_in[9];
    const float* wo = (const float*)d_in[10];
    const float* bo = (const float*)d_in[11];
    float* out = (float*)d_out;

    __half *xa, *wf, *qf, *kf, *vt, *om;
    cudaGetSymbolAddress((void**)&xa, g_xa);
    cudaGetSymbolAddress((void**)&wf, g_w);
    cudaGetSymbolAddress((void**)&qf, g_q);
    cudaGetSymbolAddress((void**)&kf, g_k);
    cudaGetSymbolAddress((void**)&vt, g_vt);
    cudaGetSymbolAddress((void**)&om, g_om);

    cudaFuncSetAttribute(gemm_mma<0>, cudaFuncAttributeMaxDynamicSharedMemorySize, GSMEM);
    cudaFuncSetAttribute(gemm_mma<1>, cudaFuncAttributeMaxDynamicSharedMemorySize, GSMEM);
    cudaFuncSetAttribute(gemm_mma<2>, cudaFuncAttributeMaxDynamicSharedMemorySize, GSMEM);
    cudaFuncSetAttribute(attn_mma, cudaFuncAttributeMaxDynamicSharedMemorySize, ASMEM);

    const int nx4 = MTOT * DM / 4;
    const int nw4 = DM * DM / 4;
    dim3 gg(DM / 128, MTOT / 128);

    trunc_x<<<(nx4 + 255) / 256, 256>>>(q, xa, nx4);
    trunc_x<<<(nw4 + 255) / 256, 256>>>(wq, wf, nw4);
    gemm_mma<1><<<gg, 256, GSMEM>>>(xa, wf, bq, nullptr, qf);

    trunc_x<<<(nx4 + 255) / 256, 256>>>(k, xa, nx4);
    trunc_x<<<(nw4 + 255) / 256, 256>>>(wk, wf, nw4);
    gemm_mma<1><<<gg, 256, GSMEM>>>(xa, wf, bk, nullptr, kf);

    trunc_x<<<(nx4 + 255) / 256, 256>>>(v, xa, nx4);
    trunc_x<<<(nw4 + 255) / 256, 256>>>(wv, wf, nw4);
    gemm_mma<2><<<gg, 256, GSMEM>>>(xa, wf, bv, nullptr, vt);

    dim3 ga(S_LEN / 128, B_SZ * NH);
    attn_mma<<<ga, 256, ASMEM>>>(qf, kf, vt, mk, om);

    trunc_x<<<(nw4 + 255) / 256, 256>>>(wo, wf, nw4);
    gemm_mma<0><<<gg, 256, GSMEM>>>(om, wf, bo, out, nullptr);
}

// round 9
// speedup vs baseline: 6.3079x; 1.1614x over previous
#include <cuda_runtime.h>
#include <cuda_fp16.h>
#include <math.h>
#include <cstdint>

#define B_SZ  4
#define S_LEN 2048
#define DM    1024
#define NH    16
#define DK    64
#define MTOT  (B_SZ * S_LEN)   // 8192

// ---------------- scratch (device globals) ----------------
__device__ __half g_xa3[(size_t)3 * MTOT * DM];     // truncated q,k,v activations
__device__ __half g_w4[(size_t)4 * DM * DM];        // truncated wq,wk,wv,wo
__device__ __half g_q[(size_t)B_SZ * NH * S_LEN * DK];
__device__ __half g_k[(size_t)B_SZ * NH * S_LEN * DK];
__device__ __half g_vt[(size_t)B_SZ * NH * DK * S_LEN];   // V^T
__device__ __half g_om[(size_t)MTOT * DM];

// ---------------- helpers ----------------
__device__ __forceinline__ uint32_t smem_u32(const void* p) {
    uint32_t a;
    asm("{ .reg .u64 t; cvta.to.shared.u64 t, %1; cvt.u32.u64 %0, t; }" : "=r"(a) : "l"(p));
    return a;
}
__device__ __forceinline__ void cp16(uint32_t dst, const void* src) {
    asm volatile("cp.async.cg.shared.global [%0], [%1], 16;" :: "r"(dst), "l"(src) : "memory");
}
#define CP_COMMIT() asm volatile("cp.async.commit_group;" ::: "memory")
#define CP_WAIT(n)  asm volatile("cp.async.wait_group %0;" :: "n"(n) : "memory")

__device__ __forceinline__ void mma_f16(float* d, const uint32_t* a, const uint32_t* b) {
    asm volatile(
        "mma.sync.aligned.m16n8k16.row.col.f32.f16.f16.f32 "
        "{%0,%1,%2,%3}, {%4,%5,%6,%7}, {%8,%9}, {%0,%1,%2,%3};"
        : "+f"(d[0]), "+f"(d[1]), "+f"(d[2]), "+f"(d[3])
        : "r"(a[0]), "r"(a[1]), "r"(a[2]), "r"(a[3]), "r"(b[0]), "r"(b[1]));
}
__device__ __forceinline__ void ldm_x4(uint32_t* r, uint32_t addr) {
    asm volatile("ldmatrix.sync.aligned.m8n8.x4.shared.b16 {%0,%1,%2,%3}, [%4];"
        : "=r"(r[0]), "=r"(r[1]), "=r"(r[2]), "=r"(r[3]) : "r"(addr));
}
__device__ __forceinline__ uint32_t packh(float a, float b) {
    __half2 t = __floats2half2_rn(a, b);
    return *(uint32_t*)&t;
}

// ---------------- fp32 -> fp16 truncation (merged launches) ----------------
__global__ void __launch_bounds__(256) trunc3(const float* __restrict__ x0,
                                              const float* __restrict__ x1,
                                              const float* __restrict__ x2,
                                              __half* __restrict__ o, int n4)
{
    const int i = blockIdx.x * 256 + threadIdx.x;
    if (i >= n4) return;
    const float* x = (blockIdx.y == 0) ? x0 : (blockIdx.y == 1) ? x1 : x2;
    __half* d = o + (size_t)blockIdx.y * n4 * 4;
    float4 v = ((const float4*)x)[i];
    ((__half2*)d)[i * 2 + 0] = __floats2half2_rn(v.x, v.y);
    ((__half2*)d)[i * 2 + 1] = __floats2half2_rn(v.z, v.w);
}

__global__ void __launch_bounds__(256) trunc4(const float* __restrict__ x0,
                                              const float* __restrict__ x1,
                                              const float* __restrict__ x2,
                                              const float* __restrict__ x3,
                                              __half* __restrict__ o, int n4)
{
    const int i = blockIdx.x * 256 + threadIdx.x;
    if (i >= n4) return;
    const float* x = (blockIdx.y == 0) ? x0 : (blockIdx.y == 1) ? x1
                   : (blockIdx.y == 2) ? x2 : x3;
    __half* d = o + (size_t)blockIdx.y * n4 * 4;
    float4 v = ((const float4*)x)[i];
    ((__half2*)d)[i * 2 + 0] = __floats2half2_rn(v.x, v.y);
    ((__half2*)d)[i * 2 + 1] = __floats2half2_rn(v.z, v.w);
}

// ---------------- fp16 mma.sync GEMM core ----------------
#define BK        32
#define NCHUNK    (DM / BK)
#define ASTRIDE_B 80
#define TILE_B    (128 * ASTRIDE_B)
#define GSMEM     (2 * 2 * TILE_B)      // 40960

struct GemmAcc { float a[4][4][4]; };

__device__ __forceinline__ void gemm_mainloop(const __half* __restrict__ A,
                                              const __half* __restrict__ B,
                                              uint32_t smb, int tid, int m0, int n0,
                                              GemmAcc& G)
{
    const int w  = tid >> 5;
    const int l  = tid & 31;
    const int wm = (w & 1) * 64;
    const int wn = (w >> 1) * 32;

    const int r0 = tid >> 2, c0 = tid & 3;
    const int r1 = (tid + 256) >> 2, c1 = (tid + 256) & 3;

    auto buf_off = [](int buf, int t) -> uint32_t {
        return (uint32_t)(buf * 2 + t) * TILE_B;
    };
    auto load_chunk = [&](int ck, int buf) {
        const size_t ko = (size_t)ck * BK;
        const uint32_t s0 = (uint32_t)r0 * ASTRIDE_B + c0 * 16;
        const uint32_t s1 = (uint32_t)r1 * ASTRIDE_B + c1 * 16;
        cp16(smb + buf_off(buf, 0) + s0, A + (size_t)(m0 + r0) * DM + ko + c0 * 8);
        cp16(smb + buf_off(buf, 0) + s1, A + (size_t)(m0 + r1) * DM + ko + c1 * 8);
        cp16(smb + buf_off(buf, 1) + s0, B + (size_t)(n0 + r0) * DM + ko + c0 * 8);
        cp16(smb + buf_off(buf, 1) + s1, B + (size_t)(n0 + r1) * DM + ko + c1 * 8);
        CP_COMMIT();
    };

#pragma unroll
    for (int mi = 0; mi < 4; ++mi)
#pragma unroll
        for (int ni = 0; ni < 4; ++ni)
#pragma unroll
            for (int j = 0; j < 4; ++j) G.a[mi][ni][j] = 0.f;

    load_chunk(0, 0);

    const int g    = l >> 3;
    const int arow = (g & 1) * 8 + (l & 7);
    const int acol = (g >> 1) * 16;
    const int brow = (g >> 1) * 8 + (l & 7);
    const int bcol = (g & 1) * 16;

    for (int ck = 0; ck < NCHUNK; ++ck) {
        const int buf = ck & 1;
        if (ck + 1 < NCHUNK) {
            load_chunk(ck + 1, buf ^ 1);
            CP_WAIT(1);
        } else {
            CP_WAIT(0);
        }
        __syncthreads();

        const uint32_t sA = smb + buf_off(buf, 0);
        const uint32_t sB = smb + buf_off(buf, 1);

#pragma unroll
        for (int kk = 0; kk < BK; kk += 16) {
            uint32_t af[4][4], bf[4][2];
#pragma unroll
            for (int mi = 0; mi < 4; ++mi)
                ldm_x4(af[mi], sA + (uint32_t)(wm + mi * 16 + arow) * ASTRIDE_B + kk * 2 + acol);
#pragma unroll
            for (int p = 0; p < 2; ++p) {
                uint32_t rh[4];
                ldm_x4(rh, sB + (uint32_t)(wn + p * 16 + brow) * ASTRIDE_B + kk * 2 + bcol);
                bf[2 * p][0] = rh[0]; bf[2 * p][1] = rh[1];
                bf[2 * p + 1][0] = rh[2]; bf[2 * p + 1][1] = rh[3];
            }
#pragma unroll
            for (int mi = 0; mi < 4; ++mi)
#pragma unroll
                for (int ni = 0; ni < 4; ++ni)
                    mma_f16(G.a[mi][ni], af[mi], bf[ni]);
        }
        __syncthreads();
    }
}

// fused Q/K/V projection: blockIdx.z selects activation, weight slice, bias, epilogue.
__global__ void __launch_bounds__(256, 2) gemm_qkv(const __half* __restrict__ XA3,
                                                   const __half* __restrict__ W4,
                                                   const float* __restrict__ bq,
                                                   const float* __restrict__ bk,
                                                   const float* __restrict__ bv,
                                                   __half* __restrict__ qf,
                                                   __half* __restrict__ kf,
                                                   __half* __restrict__ vt)
{
    extern __shared__ char smem[];
    const uint32_t smb = smem_u32(smem);
    const int tid = threadIdx.x;
    const int z   = blockIdx.z;
    const int m0  = blockIdx.y * 128;
    const int n0  = blockIdx.x * 128;

    const __half* A = XA3 + (size_t)z * MTOT * DM;
    const __half* B = W4 + (size_t)z * DM * DM;
    const float* bias = (z == 0) ? bq : (z == 1) ? bk : bv;

    GemmAcc G;
    gemm_mainloop(A, B, smb, tid, m0, n0, G);

    const int w  = tid >> 5;
    const int l  = tid & 31;
    const int wm = (w & 1) * 64;
    const int wn = (w >> 1) * 32;
    const int lr = l >> 2;

#pragma unroll
    for (int mi = 0; mi < 4; ++mi) {
        const int mrow = m0 + wm + mi * 16 + lr;
        const int b = mrow >> 11;
        const int s = mrow & (S_LEN - 1);
#pragma unroll
        for (int ni = 0; ni < 4; ++ni) {
            const int col = n0 + wn + ni * 8 + (l & 3) * 2;
            const float2 b2 = *(const float2*)&bias[col];
            float2 v0 = { G.a[mi][ni][0] + b2.x, G.a[mi][ni][1] + b2.y };
            float2 v1 = { G.a[mi][ni][2] + b2.x, G.a[mi][ni][3] + b2.y };
            const int hd = col >> 6, d = col & 63;
            if (z < 2) {
                __half* oh = (z == 0) ? qf : kf;
                const size_t base = ((size_t)(b * NH + hd) * S_LEN + s) * DK + d;
                *(uint32_t*)&oh[base] = packh(v0.x, v0.y);
                *(uint32_t*)&oh[base + 8 * DK] = packh(v1.x, v1.y);
            } else {
                const size_t rb = ((size_t)(b * NH + hd) * DK + d) * S_LEN;
                vt[rb + s] = __float2half_rn(v0.x);
                vt[rb + S_LEN + s] = __float2half_rn(v0.y);
                vt[rb + s + 8] = __float2half_rn(v1.x);
                vt[rb + S_LEN + s + 8] = __float2half_rn(v1.y);
            }
        }
    }
}

// output projection: fp32 row-major out
__global__ void __launch_bounds__(256, 2) gemm_out(const __half* __restrict__ A,
                                                   const __half* __restrict__ B,
                                                   const float* __restrict__ bias,
                                                   float* __restrict__ out)
{
    extern __shared__ char smem[];
    const uint32_t smb = smem_u32(smem);
    const int tid = threadIdx.x;
    const int m0  = blockIdx.y * 128;
    const int n0  = blockIdx.x * 128;

    GemmAcc G;
    gemm_mainloop(A, B, smb, tid, m0, n0, G);

    const int w  = tid >> 5;
    const int l  = tid & 31;
    const int wm = (w & 1) * 64;
    const int wn = (w >> 1) * 32;
    const int lr = l >> 2;

#pragma unroll
    for (int mi = 0; mi < 4; ++mi) {
        const int mrow = m0 + wm + mi * 16 + lr;
#pragma unroll
        for (int ni = 0; ni < 4; ++ni) {
            const int col = n0 + wn + ni * 8 + (l & 3) * 2;
            const float2 b2 = *(const float2*)&bias[col];
            float2 v0 = { G.a[mi][ni][0] + b2.x, G.a[mi][ni][1] + b2.y };
            float2 v1 = { G.a[mi][ni][2] + b2.x, G.a[mi][ni][3] + b2.y };
            *(float2*)&out[(size_t)mrow * DM + col] = v0;
            *(float2*)&out[(size_t)(mrow + 8) * DM + col] = v1;
        }
    }
}

// ---------------- fp16 mma.sync flash attention (single-product) ----------------
#define RSTR      144
#define AOFF_Q    0
#define AOFF_K    18432
#define AOFF_V    36864
#define AOFF_MSK  55296
#define ASMEM     63488

__global__ void __launch_bounds__(256, 1) attn_mma(const __half* __restrict__ Q,
                                                   const __half* __restrict__ K,
                                                   const __half* __restrict__ V,
                                                   const int* __restrict__ mask,
                                                   __half* __restrict__ om)
{
    extern __shared__ char smem[];
    const uint32_t smb = smem_u32(smem);
    const int tid = threadIdx.x;
    const int w   = tid >> 5;
    const int l   = tid & 31;
    const int bh  = blockIdx.y;
    const int bb  = bh >> 4;
    const int hh  = bh & 15;
    const int q0  = blockIdx.x * 128;
    const int wq0 = w * 16;
    const int r   = l >> 2;
    const int cg  = l & 3;

    const int g    = l >> 3;
    const int arow = (g & 1) * 8 + (l & 7);
    const int acol = (g >> 1) * 16;
    const int brow = (g >> 1) * 8 + (l & 7);
    const int bcol = (g & 1) * 16;

#pragma unroll
    for (int p = 0; p < 4; ++p) {
        const int idx = tid + p * 256;
        const int row = idx >> 3, ci = idx & 7;
        cp16(smb + AOFF_Q + row * RSTR + ci * 16,
             Q + ((size_t)bh * S_LEN + q0 + row) * DK + ci * 8);
    }

    auto load_kv = [&](int kt, int buf) {
#pragma unroll
        for (int p = 0; p < 2; ++p) {
            const int idx = tid + p * 256;
            const int row = idx >> 3, ci = idx & 7;
            const uint32_t dst = (uint32_t)row * RSTR + ci * 16 + buf * 9216;
            cp16(smb + AOFF_K + dst, K + ((size_t)bh * S_LEN + kt + row) * DK + ci * 8);
            cp16(smb + AOFF_V + dst, V + ((size_t)bh * DK + row) * S_LEN + kt + ci * 8);
        }
        CP_COMMIT();
    };
    load_kv(0, 0);

    int* msks = (int*)(smem + AOFF_MSK);
#pragma unroll
    for (int p = 0; p < 2; ++p) {
        const int i = tid + p * 256;
        *(int4*)&msks[i * 4] = *(const int4*)&mask[(size_t)bb * S_LEN + i * 4];
    }

    uint32_t qf[4][4];
    float o[8][4];
#pragma unroll
    for (int nj = 0; nj < 8; ++nj)
#pragma unroll
        for (int j = 0; j < 4; ++j) o[nj][j] = 0.f;
    float m0 = -INFINITY, m1 = -INFINITY, l0 = 0.f, l1 = 0.f;

    const int NIT = S_LEN / 64;
    for (int it = 0; it < NIT; ++it) {
        const int kt = it * 64;
        const int buf = it & 1;
        if (it + 1 < NIT) {
            load_kv(kt + 64, buf ^ 1);
            CP_WAIT(1);
        } else {
            CP_WAIT(0);
        }
        __syncthreads();

        if (it == 0) {
#pragma unroll
            for (int k = 0; k < 4; ++k)
                ldm_x4(qf[k], smb + AOFF_Q + (uint32_t)(wq0 + arow) * RSTR + k * 32 + acol);
        }

        float s[8][4];
#pragma unroll
        for (int nj = 0; nj < 8; ++nj)
#pragma unroll
            for (int j = 0; j < 4; ++j) s[nj][j] = 0.f;

#pragma unroll
        for (int k = 0; k < 4; ++k)
#pragma unroll
            for (int p = 0; p < 4; ++p) {
                const uint32_t kb = (uint32_t)(p * 16 + brow) * RSTR + k * 32 + bcol + buf * 9216;
                uint32_t rh[4];
                ldm_x4(rh, smb + AOFF_K + kb);
                mma_f16(s[2 * p],     qf[k], rh);
                mma_f16(s[2 * p + 1], qf[k], rh + 2);
            }

        float mx0 = -INFINITY, mx1 = -INFINITY;
#pragma unroll
        for (int nj = 0; nj < 8; ++nj) {
            const int kc = kt + nj * 8 + cg * 2;
            const bool a0 = msks[kc] != 0;
            const bool a1 = msks[kc + 1] != 0;
            s[nj][0] = a0 ? s[nj][0] * 0.125f : -1e9f;
            s[nj][1] = a1 ? s[nj][1] * 0.125f : -1e9f;
            s[nj][2] = a0 ? s[nj][2] * 0.125f : -1e9f;
            s[nj][3] = a1 ? s[nj][3] * 0.125f : -1e9f;
            mx0 = fmaxf(mx0, fmaxf(s[nj][0], s[nj][1]));
            mx1 = fmaxf(mx1, fmaxf(s[nj][2], s[nj][3]));
        }
        mx0 = fmaxf(mx0, __shfl_xor_sync(0xffffffffu, mx0, 1));
        mx0 = fmaxf(mx0, __shfl_xor_sync(0xffffffffu, mx0, 2));
        mx1 = fmaxf(mx1, __shfl_xor_sync(0xffffffffu, mx1, 1));
        mx1 = fmaxf(mx1, __shfl_xor_sync(0xffffffffu, mx1, 2));

        const float nm0 = fmaxf(m0, mx0);
        const float nm1 = fmaxf(m1, mx1);
        const float f0 = __expf(m0 - nm0);
        const float f1 = __expf(m1 - nm1);
        m0 = nm0; m1 = nm1;

        uint32_t ph[4][4];
        float la0 = 0.f, la1 = 0.f;
#pragma unroll
        for (int nj = 0; nj < 8; ++nj) {
            const float p0 = __expf(s[nj][0] - m0);
            const float p1 = __expf(s[nj][1] - m0);
            const float p2 = __expf(s[nj][2] - m1);
            const float p3 = __expf(s[nj][3] - m1);
            la0 += p0 + p1;
            la1 += p2 + p3;
            const int t = nj >> 1;
            if ((nj & 1) == 0) {
                ph[t][0] = packh(p0, p1);
                ph[t][1] = packh(p2, p3);
            } else {
                ph[t][2] = packh(p0, p1);
                ph[t][3] = packh(p2, p3);
            }
        }
        la0 += __shfl_xor_sync(0xffffffffu, la0, 1);
        la0 += __shfl_xor_sync(0xffffffffu, la0, 2);
        la1 += __shfl_xor_sync(0xffffffffu, la1, 1);
        la1 += __shfl_xor_sync(0xffffffffu, la1, 2);
        l0 = l0 * f0 + la0;
        l1 = l1 * f1 + la1;

#pragma unroll
        for (int nj = 0; nj < 8; ++nj) {
            o[nj][0] *= f0; o[nj][1] *= f0;
            o[nj][2] *= f1; o[nj][3] *= f1;
        }

#pragma unroll
        for (int t = 0; t < 4; ++t)
#pragma unroll
            for (int p = 0; p < 4; ++p) {
                const uint32_t vb = (uint32_t)(p * 16 + brow) * RSTR + t * 32 + bcol + buf * 9216;
                uint32_t rh[4];
                ldm_x4(rh, smb + AOFF_V + vb);
                mma_f16(o[2 * p],     ph[t], rh);
                mma_f16(o[2 * p + 1], ph[t], rh + 2);
            }
        __syncthreads();
    }

    const float inv0 = 1.f / l0;
    const float inv1 = 1.f / l1;
    const int s0r = q0 + wq0 + r;
    const int s1r = s0r + 8;
#pragma unroll
    for (int nj = 0; nj < 8; ++nj) {
        const int col = hh * 64 + nj * 8 + cg * 2;
        float x0 = o[nj][0] * inv0, y0 = o[nj][1] * inv0;
        float x1 = o[nj][2] * inv1, y1 = o[nj][3] * inv1;
        *(uint32_t*)&om[((size_t)(bb * S_LEN + s0r)) * DM + col] = packh(x0, y0);
        *(uint32_t*)&om[((size_t)(bb * S_LEN + s1r)) * DM + col] = packh(x1, y1);
    }
}

// ---------------- launch ----------------
extern "C" void kernel_launch(void* const* d_in, const int* in_sizes, int n_in,
                              void* d_out, int out_size) {
    const float* q  = (const float*)d_in[0];
    const float* k  = (const float*)d_in[1];
    const float* v  = (const float*)d_in[2];
    const int*   mk = (const int*)  d_in[3];
    const float* wq = (const float*)d_in[4];
    const float* bq = (const float*)d_in[5];
    const float* wk = (const float*)d_in[6];
    const float* bk = (const float*)d_in[7];
    const float* wv = (const float*)d_in[8];
    const float* bv = (const float*)d_in[9];
    const float* wo = (const float*)d_in[10];
    const float* bo = (const float*)d_in[11];
    float* out = (float*)d_out;

    __half *xa3, *w4, *qf, *kf, *vt, *om;
    cudaGetSymbolAddress((void**)&xa3, g_xa3);
    cudaGetSymbolAddress((void**)&w4, g_w4);
    cudaGetSymbolAddress((void**)&qf, g_q);
    cudaGetSymbolAddress((void**)&kf, g_k);
    cudaGetSymbolAddress((void**)&vt, g_vt);
    cudaGetSymbolAddress((void**)&om, g_om);

    cudaFuncSetAttribute(gemm_qkv, cudaFuncAttributeMaxDynamicSharedMemorySize, GSMEM);
    cudaFuncSetAttribute(gemm_out, cudaFuncAttributeMaxDynamicSharedMemorySize, GSMEM);
    cudaFuncSetAttribute(attn_mma, cudaFuncAttributeMaxDynamicSharedMemorySize, ASMEM);

    const int nx4 = MTOT * DM / 4;
    const int nw4 = DM * DM / 4;

    // preprocessing: 2 launches
    trunc3<<<dim3((nx4 + 255) / 256, 3), 256>>>(q, k, v, xa3, nx4);
    trunc4<<<dim3((nw4 + 255) / 256, 4), 256>>>(wq, wk, wv, wo, w4, nw4);

    // fused Q/K/V projections: 1 launch, 1536 CTAs
    dim3 gqkv(DM / 128, MTOT / 128, 3);
    gemm_qkv<<<gqkv, 256, GSMEM>>>(xa3, w4, bq, bk, bv, qf, kf, vt);

    // attention
    dim3 ga(S_LEN / 128, B_SZ * NH);
    attn_mma<<<ga, 256, ASMEM>>>(qf, kf, vt, mk, om);

    // output projection
    dim3 gg(DM / 128, MTOT / 128);
    gemm_out<<<gg, 256, GSMEM>>>(om, w4 + (size_t)3 * DM * DM, bo, out);
}